// round 14
// baseline (speedup 1.0000x reference)
#include <cuda_runtime.h>
#include <cuda_fp16.h>
#include <cstdint>

// ---------------- problem constants ----------------
#define BT    128
#define NTOK  196
#define DMODEL 768
#define NHEAD 12
#define HDIM  64
#define MROWS (BT * NTOK)      // 25088
#define ATT_SCALE 0.125f
#define LOG2E 1.44269504088896f

// ---------------- scratch ----------------
__device__ __half g_At[(size_t)MROWS * DMODEL];
__device__ __half g_As[(size_t)MROWS * DMODEL];
__device__ __half g_q [(size_t)MROWS * DMODEL];
__device__ __half g_kv[(size_t)MROWS * 2 * DMODEL];
__device__ __half g_o [(size_t)MROWS * DMODEL];
__device__ __half g_qw [DMODEL * DMODEL];
__device__ __half g_kvw[2 * DMODEL * DMODEL];
__device__ __half g_pw [DMODEL * DMODEL];
__device__ float  g_qb2[DMODEL];

// ---------------- helpers ----------------
__device__ __forceinline__ void mma16b(float* c, const uint32_t* a, uint32_t b0, uint32_t b1) {
    asm volatile(
        "mma.sync.aligned.m16n8k16.row.col.f32.f16.f16.f32 "
        "{%0,%1,%2,%3}, {%4,%5,%6,%7}, {%8,%9}, {%0,%1,%2,%3};\n"
        : "+f"(c[0]), "+f"(c[1]), "+f"(c[2]), "+f"(c[3])
        : "r"(a[0]), "r"(a[1]), "r"(a[2]), "r"(a[3]), "r"(b0), "r"(b1));
}

__device__ __forceinline__ void ldsm4(uint32_t saddr, uint32_t* r) {
    asm volatile("ldmatrix.sync.aligned.m8n8.x4.shared.b16 {%0,%1,%2,%3}, [%4];"
                 : "=r"(r[0]), "=r"(r[1]), "=r"(r[2]), "=r"(r[3]) : "r"(saddr));
}

__device__ __forceinline__ void ldsm4t(uint32_t saddr, uint32_t* r) {
    asm volatile("ldmatrix.sync.aligned.m8n8.x4.trans.shared.b16 {%0,%1,%2,%3}, [%4];"
                 : "=r"(r[0]), "=r"(r[1]), "=r"(r[2]), "=r"(r[3]) : "r"(saddr));
}

__device__ __forceinline__ void cp16(uint32_t saddr, const void* gptr) {
    asm volatile("cp.async.cg.shared.global [%0], [%1], 16;\n"
                 :: "r"(saddr), "l"(gptr) : "memory");
}

__device__ __forceinline__ void cp16z(uint32_t saddr, const void* gptr, int src_bytes) {
    asm volatile("cp.async.cg.shared.global [%0], [%1], 16, %2;\n"
                 :: "r"(saddr), "l"(gptr), "r"(src_bytes) : "memory");
}

__device__ __forceinline__ uint32_t pack2h(float a, float b) {
    __half2 h = __floats2half2_rn(a, b);
    return *(uint32_t*)&h;
}

__device__ __forceinline__ void ex2x2(uint32_t& x) {
    asm volatile("ex2.approx.f16x2 %0, %0;" : "+r"(x));
}

__device__ __forceinline__ float2 h22f2(uint32_t x) {
    return __half22float2(*(__half2*)&x);
}

// ---------------- merged prep + weight conversion (8 floats / thread) ---------
#define C4 (DMODEL / 4)
#define C8 (DMODEL / 8)
#define TCH (MROWS * C8)
#define WN4 (DMODEL * DMODEL / 4)
#define WCH (WN4 / 2)
#define QSCL (ATT_SCALE * LOG2E)
#define PC_TOTAL (2 * TCH + 4 * WCH + DMODEL / 4)

__device__ __forceinline__ uint4 cvt8(float4 a0, float4 a1, float4 p0, float4 p1) {
    uint4 o;
    o.x = pack2h(a0.x + p0.x, a0.y + p0.y);
    o.y = pack2h(a0.z + p0.z, a0.w + p0.w);
    o.z = pack2h(a1.x + p1.x, a1.y + p1.y);
    o.w = pack2h(a1.z + p1.z, a1.w + p1.w);
    return o;
}

__device__ __forceinline__ uint4 cvt8s(float4 a0, float4 a1, float s) {
    uint4 o;
    o.x = pack2h(a0.x * s, a0.y * s);
    o.y = pack2h(a0.z * s, a0.w * s);
    o.z = pack2h(a1.x * s, a1.y * s);
    o.w = pack2h(a1.z * s, a1.w * s);
    return o;
}

__global__ void prepconv_kernel(const float4* __restrict__ t_x,
                                const float4* __restrict__ s_x,
                                const float4* __restrict__ vmae_pos,
                                const float4* __restrict__ clip_pos,
                                const float4* __restrict__ q_w,
                                const float4* __restrict__ kv_w,
                                const float4* __restrict__ proj_w,
                                const float4* __restrict__ q_b,
                                uint4* __restrict__ At, uint4* __restrict__ As,
                                uint4* __restrict__ qw, uint4* __restrict__ kvw,
                                uint4* __restrict__ pw, float4* __restrict__ qb2) {
    int idx = blockIdx.x * blockDim.x + threadIdx.x;
    if (idx < TCH) {
        int m = idx / C8;
        int c = idx - m * C8;
        const float4* a = t_x + (size_t)m * C4 + 2 * c;
        const float4* p = vmae_pos + (m % NTOK) * C4 + 2 * c;
        float4 a0 = a[0], a1 = a[1];
        float4 p0 = p[0], p1 = p[1];
        At[idx] = cvt8(a0, a1, p0, p1);
    } else if (idx < 2 * TCH) {
        int i = idx - TCH;
        int m = i / C8;
        int c = i - m * C8;
        int src_row = m + m / NTOK + 1;       // skip CLS each frame
        const float4* a = s_x + (size_t)src_row * C4 + 2 * c;
        const float4* p = clip_pos + (m % NTOK) * C4 + 2 * c;
        float4 a0 = a[0], a1 = a[1];
        float4 p0 = p[0], p1 = p[1];
        As[i] = cvt8(a0, a1, p0, p1);
    } else {
        int i = idx - 2 * TCH;
        if (i < WCH) {
            qw[i] = cvt8s(q_w[2 * i], q_w[2 * i + 1], QSCL);
        } else if (i < 3 * WCH) {
            int j = i - WCH;
            kvw[j] = cvt8s(kv_w[2 * j], kv_w[2 * j + 1], 1.f);
        } else if (i < 4 * WCH) {
            int j = i - 3 * WCH;
            pw[j] = cvt8s(proj_w[2 * j], proj_w[2 * j + 1], 1.f);
        } else if (i < 4 * WCH + DMODEL / 4) {
            int j = i - 4 * WCH;
            float4 v = q_b[j];
            v.x *= QSCL; v.y *= QSCL; v.z *= QSCL; v.w *= QSCL;
            qb2[j] = v;
        }
    }
}

// ---------------- fp16 GEMM core: 256 thr, 8 warps 32x64, BK=64, XOR swizzle -----
// Manual fragment ping-pong: LDSM prefetch interleaved between MMA groups to
// keep crossbar and tensor pipes simultaneously busy (anti phase-lock).
#define LDHB 128
#define GTILE_B (128 * LDHB)        // 16384 B
#define GSTG_B  (2 * GTILE_B)       // 32768 B
#define GSMEM   (3 * GSTG_B)        // 98304 B

__device__ __forceinline__ void fill_chunk_f16(uint32_t sbase, int stage,
                                               const __half* A, const __half* W,
                                               int bm, int bn, int kt, int tid, int qc) {
    uint32_t ab = sbase + stage * GSTG_B;
    uint32_t bb = ab + GTILE_B;
    #pragma unroll
    for (int it = 2 * qc; it < 2 * qc + 2; it++) {
        int c = tid + it * 256;
        int row, ch;
        if (c < 1024) {
            row = c >> 3; ch = c & 7;
            const __half* g = A + (size_t)(bm * 128 + row) * DMODEL + kt * 64 + ch * 8;
            cp16(ab + (row << 7) + (((uint32_t)(ch ^ (row & 7))) << 4), g);
        } else {
            int c2 = c - 1024;
            row = c2 >> 3; ch = c2 & 7;
            const __half* g = W + (size_t)(bn * 128 + row) * DMODEL + kt * 64 + ch * 8;
            cp16(bb + (row << 7) + (((uint32_t)(ch ^ (row & 7))) << 4), g);
        }
    }
}

template <bool HALF_OUT>
__device__ __forceinline__ void gemm_core(const __half* __restrict__ A,
                                          const __half* __restrict__ W,
                                          const float* __restrict__ bias,
                                          void* __restrict__ Cout,
                                          int Ncols, int bn, int bm,
                                          uint32_t sbase) {
    const int tid  = threadIdx.x;
    const int lane = tid & 31;
    const int w    = tid >> 5;
    const int wm   = (w & 3) * 32;
    const int wn   = (w >> 2) * 64;
    const int gr   = lane >> 2;
    const int tg   = lane & 3;
    const int lr   = lane & 15;
    const int lh   = lane >> 4;
    const uint32_t sw = (uint32_t)(lr & 7);

    uint32_t arow[2], brow[4];
    #pragma unroll
    for (int i = 0; i < 2; i++)  arow[i] = (uint32_t)(wm + i * 16 + lr) << 7;
    #pragma unroll
    for (int jb = 0; jb < 4; jb++) brow[jb] = (uint32_t)(wn + jb * 16 + lr) << 7;

    float acc[2][8][4];
    #pragma unroll
    for (int i = 0; i < 2; i++)
        #pragma unroll
        for (int j = 0; j < 8; j++)
            #pragma unroll
            for (int r = 0; r < 4; r++) acc[i][j][r] = 0.f;

    #pragma unroll
    for (int pk = 0; pk < 2; pk++) {
        #pragma unroll
        for (int qc = 0; qc < 4; qc++)
            fill_chunk_f16(sbase, pk, A, W, bm, bn, pk, tid, qc);
        asm volatile("cp.async.commit_group;\n" ::: "memory");
    }

    for (int kt = 0; kt < 12; kt++) {
        if (kt < 11) asm volatile("cp.async.wait_group 1;\n" ::: "memory");
        else         asm volatile("cp.async.wait_group 0;\n" ::: "memory");
        __syncthreads();

        const bool do_fill = (kt + 2 < 12);
        const int fstage = (kt + 2) % 3;

        const uint32_t sAs = sbase + (uint32_t)((kt % 3) * GSTG_B);
        const uint32_t sBs = sAs + GTILE_B;

        // fragment ping-pong buffers (register-neutral vs burst version)
        uint32_t af[2][2][4];      // [buf][i][frag]
        uint32_t bf[2][4];         // [buf][frag]

        // preload k16=0: A both halves + B block 0
        {
            const uint32_t pc0 = ((uint32_t)lh ^ sw) << 4;
            ldsm4(sAs + arow[0] + pc0, af[0][0]);
            ldsm4(sAs + arow[1] + pc0, af[0][1]);
            ldsm4(sBs + brow[0] + pc0, bf[0]);
        }

        #pragma unroll
        for (int k16 = 0; k16 < 4; k16++) {
            if (do_fill)
                fill_chunk_f16(sbase, fstage, A, W, bm, bn, kt + 2, tid, k16);

            const int ab = k16 & 1;
            const uint32_t pc  = (((uint32_t)(2 * k16 + lh)) ^ sw) << 4;
            const uint32_t pcn = (((uint32_t)(2 * k16 + 2 + lh)) ^ sw) << 4;

            #pragma unroll
            for (int jb = 0; jb < 4; jb++) {
                const int bb_ = jb & 1;   // (4*k16 + jb) & 1 == jb & 1
                // prefetch next fragments BEFORE this group's MMAs (indep regs)
                if (jb < 3) {
                    ldsm4(sBs + brow[jb + 1] + pc, bf[bb_ ^ 1]);
                } else if (k16 < 3) {
                    ldsm4(sAs + arow[0] + pcn, af[ab ^ 1][0]);
                    ldsm4(sAs + arow[1] + pcn, af[ab ^ 1][1]);
                    ldsm4(sBs + brow[0] + pcn, bf[bb_ ^ 1]);
                }
                // 16 MMAs on current fragments
                #pragma unroll
                for (int i = 0; i < 2; i++) {
                    mma16b(acc[i][2 * jb],     af[ab][i], bf[bb_][0], bf[bb_][2]);
                    mma16b(acc[i][2 * jb + 1], af[ab][i], bf[bb_][1], bf[bb_][3]);
                }
            }
        }
        if (do_fill)
            asm volatile("cp.async.commit_group;\n" ::: "memory");
    }

    #pragma unroll
    for (int i = 0; i < 2; i++) {
        #pragma unroll
        for (int j = 0; j < 8; j++) {
            int row0 = bm * 128 + wm + i * 16 + gr;
            int col  = bn * 128 + wn + j * 8 + tg * 2;
            float b0 = bias[col], b1 = bias[col + 1];
            if (HALF_OUT) {
                __half* Ch = (__half*)Cout;
                *(__half2*)(Ch + (size_t)row0 * Ncols + col) =
                    __floats2half2_rn(acc[i][j][0] + b0, acc[i][j][1] + b1);
                *(__half2*)(Ch + (size_t)(row0 + 8) * Ncols + col) =
                    __floats2half2_rn(acc[i][j][2] + b0, acc[i][j][3] + b1);
            } else {
                float* Cf = (float*)Cout;
                float* p0 = Cf + (size_t)row0 * Ncols + col;
                float* p1 = Cf + (size_t)(row0 + 8) * Ncols + col;
                p0[0] = acc[i][j][0] + b0;
                p0[1] = acc[i][j][1] + b1;
                p1[0] = acc[i][j][2] + b0;
                p1[1] = acc[i][j][3] + b1;
            }
        }
    }
}

// fused q+kv projection: bn<6 -> q GEMM, else kv GEMM
__global__ __launch_bounds__(256, 2)
void gemm_qkv_kernel(const __half* __restrict__ At, const __half* __restrict__ qw,
                     const float* __restrict__ qb2, __half* __restrict__ qh,
                     const __half* __restrict__ As, const __half* __restrict__ kvw,
                     const float* __restrict__ kv_b, __half* __restrict__ kvh) {
    extern __shared__ __half sh[];
    const uint32_t sbase = (uint32_t)__cvta_generic_to_shared(sh);
    if (blockIdx.x < 6)
        gemm_core<true>(At, qw, qb2, qh, DMODEL, blockIdx.x, blockIdx.y, sbase);
    else
        gemm_core<true>(As, kvw, kv_b, kvh, 2 * DMODEL, blockIdx.x - 6, blockIdx.y, sbase);
}

__global__ __launch_bounds__(256, 2)
void gemm_proj_kernel(const __half* __restrict__ A, const __half* __restrict__ W,
                      const float* __restrict__ bias, float* __restrict__ C) {
    extern __shared__ __half sh[];
    const uint32_t sbase = (uint32_t)__cvta_generic_to_shared(sh);
    gemm_core<false>(A, W, bias, C, DMODEL, blockIdx.x, blockIdx.y, sbase);
}

// ---------------- fp16 flash attention: 2 CTAs per (bt,h), 7 warps x 16 q-rows ----
#define ATW 224
#define AQH 112
#define AKV 224
#define SK_OFF (AQH * 128)               // 14336
#define SV_OFF (SK_OFF + AKV * 128)      // 43008
#define ASMEM (SV_OFF + AKV * 128)       // 71680 B

__global__ __launch_bounds__(ATW, 3)
void attn_mma_kernel(const __half* __restrict__ q, const __half* __restrict__ kv,
                     __half* __restrict__ o) {
    extern __shared__ __half smh[];
    const uint32_t sbase = (uint32_t)__cvta_generic_to_shared(smh);
    const uint32_t sQa = sbase;
    const uint32_t sKa = sbase + SK_OFF;
    const uint32_t sVa = sbase + SV_OFF;

    const int b2   = blockIdx.x;
    const int bt   = b2 / (2 * NHEAD);
    const int r2   = b2 - bt * (2 * NHEAD);
    const int h    = r2 >> 1;
    const int half = r2 & 1;
    const int tid  = threadIdx.x;
    const int lane = tid & 31;
    const int w    = tid >> 5;        // 0..6
    const int gr   = lane >> 2;
    const int tg   = lane & 3;
    const int lr   = lane & 15;
    const int lh   = lane >> 4;
    const uint32_t sw = (uint32_t)(lr & 7);

    // ---- stage Q (112 rows) + K (224 rows): commit group 0 ----
    for (int idx = tid; idx < AQH * 8; idx += ATW) {
        int r = idx >> 3, ch = idx & 7;
        int grow = half * AQH + r;
        int sz = (grow < NTOK) ? 16 : 0;
        int rr = (grow < NTOK) ? grow : 0;
        uint32_t soff = ((uint32_t)r << 7) + (((uint32_t)(ch ^ (r & 7))) << 4);
        cp16z(sQa + soff, q + ((size_t)bt * NTOK + rr) * DMODEL + h * HDIM + ch * 8, sz);
    }
    for (int idx = tid; idx < AKV * 8; idx += ATW) {
        int r = idx >> 3, ch = idx & 7;
        int sz = (r < NTOK) ? 16 : 0;
        int rr = (r < NTOK) ? r : 0;
        uint32_t soff = ((uint32_t)r << 7) + (((uint32_t)(ch ^ (r & 7))) << 4);
        cp16z(sKa + soff, kv + ((size_t)bt * NTOK + rr) * (2 * DMODEL) + h * HDIM + ch * 8, sz);
    }
    asm volatile("cp.async.commit_group;\n" ::: "memory");

    // ---- stage V (224 rows): commit group 1 ----
    for (int idx = tid; idx < AKV * 8; idx += ATW) {
        int r = idx >> 3, ch = idx & 7;
        int sz = (r < NTOK) ? 16 : 0;
        int rr = (r < NTOK) ? r : 0;
        uint32_t soff = ((uint32_t)r << 7) + (((uint32_t)(ch ^ (r & 7))) << 4);
        cp16z(sVa + soff, kv + ((size_t)bt * NTOK + rr) * (2 * DMODEL) + DMODEL + h * HDIM + ch * 8, sz);
    }
    asm volatile("cp.async.commit_group;\n" ::: "memory");

    asm volatile("cp.async.wait_group 1;\n" ::: "memory");
    __syncthreads();

    // ---- preload Q A-fragments (16 rows per warp, 4 k16 chunks) ----
    const int qb = w * 16;
    const uint32_t qrow = (uint32_t)(qb + lr) << 7;
    uint32_t qa[4][4];
    #pragma unroll
    for (int kk = 0; kk < 4; kk++)
        ldsm4(sQa + qrow + ((((uint32_t)(2 * kk + lh)) ^ sw) << 4), qa[kk]);

    float oacc[8][4];
    #pragma unroll
    for (int n = 0; n < 8; n++)
        #pragma unroll
        for (int r = 0; r < 4; r++) oacc[n][r] = 0.f;
    float lsum[2] = {0.f, 0.f};

    for (int kt = 0; kt < 7; kt++) {
        float s[4][4];
        #pragma unroll
        for (int j = 0; j < 4; j++)
            #pragma unroll
            for (int r = 0; r < 4; r++) s[j][r] = 0.f;

        #pragma unroll
        for (int kk = 0; kk < 4; kk++) {
            const uint32_t pc = (((uint32_t)(2 * kk + lh)) ^ sw) << 4;
            uint32_t kb[2][4];
            #pragma unroll
            for (int jb = 0; jb < 2; jb++)
                ldsm4(sKa + (((uint32_t)(kt * 32 + jb * 16 + lr)) << 7) + pc, kb[jb]);
            #pragma unroll
            for (int j = 0; j < 4; j++)
                mma16b(s[j], qa[kk], kb[j >> 1][(j & 1)], kb[j >> 1][(j & 1) + 2]);
        }

        if (kt == 6) {
            #pragma unroll
            for (int j = 0; j < 4; j++) {
                int c0 = 192 + j * 8 + 2 * tg;
                if (c0 >= NTOK)     { s[j][0] = s[j][2] = -1e30f; }
                if (c0 + 1 >= NTOK) { s[j][1] = s[j][3] = -1e30f; }
            }
        }

        if (kt == 0) {
            asm volatile("cp.async.wait_group 0;\n" ::: "memory");
            __syncthreads();
        }

        #pragma unroll
        for (int ck = 0; ck < 2; ck++) {
            uint32_t pa[4];
            int j0 = ck * 2;
            pa[0] = pack2h(s[j0][0],     s[j0][1]);
            pa[1] = pack2h(s[j0][2],     s[j0][3]);
            pa[2] = pack2h(s[j0 + 1][0], s[j0 + 1][1]);
            pa[3] = pack2h(s[j0 + 1][2], s[j0 + 1][3]);
            ex2x2(pa[0]); ex2x2(pa[1]); ex2x2(pa[2]); ex2x2(pa[3]);

            float2 f0 = h22f2(pa[0]), f2 = h22f2(pa[2]);
            lsum[0] += (f0.x + f0.y) + (f2.x + f2.y);
            float2 f1 = h22f2(pa[1]), f3 = h22f2(pa[3]);
            lsum[1] += (f1.x + f1.y) + (f3.x + f3.y);

            int kr = kt * 32 + ck * 16;
            uint32_t vbb[4][4];
            #pragma unroll
            for (int nb = 0; nb < 4; nb++)
                ldsm4t(sVa + (((uint32_t)(kr + lr)) << 7) +
                       ((((uint32_t)(2 * nb + lh)) ^ sw) << 4), vbb[nb]);

            #pragma unroll
            for (int n = 0; n < 8; n++)
                mma16b(oacc[n], pa, vbb[n >> 1][(n & 1) * 2], vbb[n >> 1][(n & 1) * 2 + 1]);
        }
    }

    #pragma unroll
    for (int hl = 0; hl < 2; hl++) {
        lsum[hl] += __shfl_xor_sync(0xffffffffu, lsum[hl], 1);
        lsum[hl] += __shfl_xor_sync(0xffffffffu, lsum[hl], 2);
    }

    #pragma unroll
    for (int hl = 0; hl < 2; hl++) {
        float inv = 1.f / lsum[hl];
        int row = half * AQH + qb + gr + 8 * hl;
        if (row < NTOK) {
            __half* dst = o + ((size_t)bt * NTOK + row) * DMODEL + h * HDIM;
            #pragma unroll
            for (int n = 0; n < 8; n++) {
                *(__half2*)(dst + n * 8 + 2 * tg) =
                    __floats2half2_rn(oacc[n][2 * hl] * inv, oacc[n][2 * hl + 1] * inv);
            }
        }
    }
}

// ---------------- launch ----------------
extern "C" void kernel_launch(void* const* d_in, const int* in_sizes, int n_in,
                              void* d_out, int out_size) {
    const float* s_x      = (const float*)d_in[0];
    const float* t_x      = (const float*)d_in[1];
    const float* clip_pos = (const float*)d_in[2];
    const float* vmae_pos = (const float*)d_in[3];
    const float* q_w      = (const float*)d_in[4];
    const float* q_b      = (const float*)d_in[5];
    const float* kv_w     = (const float*)d_in[6];
    const float* kv_b     = (const float*)d_in[7];
    const float* proj_w   = (const float*)d_in[8];
    const float* proj_b   = (const float*)d_in[9];
    float* out = (float*)d_out;
    (void)in_sizes; (void)n_in; (void)out_size;

    __half *At, *As_, *qh, *kvh, *ob, *qw, *kvw, *pw;
    float *qb2;
    cudaGetSymbolAddress((void**)&At,  g_At);
    cudaGetSymbolAddress((void**)&As_, g_As);
    cudaGetSymbolAddress((void**)&qh,  g_q);
    cudaGetSymbolAddress((void**)&kvh, g_kv);
    cudaGetSymbolAddress((void**)&ob,  g_o);
    cudaGetSymbolAddress((void**)&qw,  g_qw);
    cudaGetSymbolAddress((void**)&kvw, g_kvw);
    cudaGetSymbolAddress((void**)&pw,  g_pw);
    cudaGetSymbolAddress((void**)&qb2, g_qb2);

    cudaFuncSetAttribute(gemm_qkv_kernel,  cudaFuncAttributeMaxDynamicSharedMemorySize, GSMEM);
    cudaFuncSetAttribute(gemm_proj_kernel, cudaFuncAttributeMaxDynamicSharedMemorySize, GSMEM);
    cudaFuncSetAttribute(attn_mma_kernel,  cudaFuncAttributeMaxDynamicSharedMemorySize, ASMEM);

    prepconv_kernel<<<(PC_TOTAL + 255) / 256, 256>>>(
        (const float4*)t_x, (const float4*)s_x,
        (const float4*)vmae_pos, (const float4*)clip_pos,
        (const float4*)q_w, (const float4*)kv_w, (const float4*)proj_w,
        (const float4*)q_b,
        (uint4*)At, (uint4*)As_, (uint4*)qw, (uint4*)kvw, (uint4*)pw,
        (float4*)qb2);

    gemm_qkv_kernel<<<dim3(18, MROWS / 128), 256, GSMEM>>>(
        At, qw, qb2, qh, As_, kvw, kv_b, kvh);

    attn_mma_kernel<<<BT * NHEAD * 2, ATW, ASMEM>>>(qh, kvh, ob);

    gemm_proj_kernel<<<dim3(DMODEL / 128, MROWS / 128), 256, GSMEM>>>(ob, pw, proj_b, out);
}

// round 15
// speedup vs baseline: 1.0113x; 1.0113x over previous
#include <cuda_runtime.h>
#include <cuda_fp16.h>
#include <cstdint>

// ---------------- problem constants ----------------
#define BT    128
#define NTOK  196
#define DMODEL 768
#define NHEAD 12
#define HDIM  64
#define MROWS (BT * NTOK)      // 25088
#define ATT_SCALE 0.125f
#define LOG2E 1.44269504088896f

// ---------------- scratch ----------------
__device__ __half g_At[(size_t)MROWS * DMODEL];
__device__ __half g_As[(size_t)MROWS * DMODEL];
__device__ __half g_q [(size_t)MROWS * DMODEL];
__device__ __half g_kv[(size_t)MROWS * 2 * DMODEL];
__device__ __half g_o [(size_t)MROWS * DMODEL];
__device__ __half g_qw [DMODEL * DMODEL];
__device__ __half g_kvw[2 * DMODEL * DMODEL];
__device__ __half g_pw [DMODEL * DMODEL];
__device__ float  g_qb2[DMODEL];

// ---------------- helpers ----------------
__device__ __forceinline__ void mma16(float* c, const uint32_t* a, const uint32_t* b) {
    asm volatile(
        "mma.sync.aligned.m16n8k16.row.col.f32.f16.f16.f32 "
        "{%0,%1,%2,%3}, {%4,%5,%6,%7}, {%8,%9}, {%0,%1,%2,%3};\n"
        : "+f"(c[0]), "+f"(c[1]), "+f"(c[2]), "+f"(c[3])
        : "r"(a[0]), "r"(a[1]), "r"(a[2]), "r"(a[3]), "r"(b[0]), "r"(b[1]));
}

__device__ __forceinline__ void ldsm4(uint32_t saddr, uint32_t* r) {
    asm volatile("ldmatrix.sync.aligned.m8n8.x4.shared.b16 {%0,%1,%2,%3}, [%4];"
                 : "=r"(r[0]), "=r"(r[1]), "=r"(r[2]), "=r"(r[3]) : "r"(saddr));
}

__device__ __forceinline__ void ldsm4t(uint32_t saddr, uint32_t* r) {
    asm volatile("ldmatrix.sync.aligned.m8n8.x4.trans.shared.b16 {%0,%1,%2,%3}, [%4];"
                 : "=r"(r[0]), "=r"(r[1]), "=r"(r[2]), "=r"(r[3]) : "r"(saddr));
}

__device__ __forceinline__ void cp16(uint32_t saddr, const void* gptr) {
    asm volatile("cp.async.cg.shared.global [%0], [%1], 16;\n"
                 :: "r"(saddr), "l"(gptr) : "memory");
}

__device__ __forceinline__ void cp16z(uint32_t saddr, const void* gptr, int src_bytes) {
    asm volatile("cp.async.cg.shared.global [%0], [%1], 16, %2;\n"
                 :: "r"(saddr), "l"(gptr), "r"(src_bytes) : "memory");
}

__device__ __forceinline__ uint32_t pack2h(float a, float b) {
    __half2 h = __floats2half2_rn(a, b);
    return *(uint32_t*)&h;
}

__device__ __forceinline__ void ex2x2(uint32_t& x) {
    asm volatile("ex2.approx.f16x2 %0, %0;" : "+r"(x));
}

__device__ __forceinline__ float2 h22f2(uint32_t x) {
    return __half22float2(*(__half2*)&x);
}

__device__ __forceinline__ float4 ldcs4(const float4* p) {
    return __ldcs(p);
}

// ---------------- merged prep + weight conversion (8 floats / thread) ---------
#define C4 (DMODEL / 4)
#define C8 (DMODEL / 8)
#define TCH (MROWS * C8)
#define WN4 (DMODEL * DMODEL / 4)
#define WCH (WN4 / 2)
#define QSCL (ATT_SCALE * LOG2E)
#define PC_TOTAL (2 * TCH + 4 * WCH + DMODEL / 4)

__device__ __forceinline__ uint4 cvt8(float4 a0, float4 a1, float4 p0, float4 p1) {
    uint4 o;
    o.x = pack2h(a0.x + p0.x, a0.y + p0.y);
    o.y = pack2h(a0.z + p0.z, a0.w + p0.w);
    o.z = pack2h(a1.x + p1.x, a1.y + p1.y);
    o.w = pack2h(a1.z + p1.z, a1.w + p1.w);
    return o;
}

__device__ __forceinline__ uint4 cvt8s(float4 a0, float4 a1, float s) {
    uint4 o;
    o.x = pack2h(a0.x * s, a0.y * s);
    o.y = pack2h(a0.z * s, a0.w * s);
    o.z = pack2h(a1.x * s, a1.y * s);
    o.w = pack2h(a1.z * s, a1.w * s);
    return o;
}

__global__ void prepconv_kernel(const float4* __restrict__ t_x,
                                const float4* __restrict__ s_x,
                                const float4* __restrict__ vmae_pos,
                                const float4* __restrict__ clip_pos,
                                const float4* __restrict__ q_w,
                                const float4* __restrict__ kv_w,
                                const float4* __restrict__ proj_w,
                                const float4* __restrict__ q_b,
                                uint4* __restrict__ At, uint4* __restrict__ As,
                                uint4* __restrict__ qw, uint4* __restrict__ kvw,
                                uint4* __restrict__ pw, float4* __restrict__ qb2) {
    int idx = blockIdx.x * blockDim.x + threadIdx.x;
    if (idx < TCH) {
        int m = idx / C8;
        int c = idx - m * C8;
        const float4* a = t_x + (size_t)m * C4 + 2 * c;
        const float4* p = vmae_pos + (m % NTOK) * C4 + 2 * c;
        float4 a0 = ldcs4(a), a1 = ldcs4(a + 1);     // streaming: read-once data
        float4 p0 = p[0], p1 = p[1];                 // pos: heavily reused, keep cached
        At[idx] = cvt8(a0, a1, p0, p1);
    } else if (idx < 2 * TCH) {
        int i = idx - TCH;
        int m = i / C8;
        int c = i - m * C8;
        int src_row = m + m / NTOK + 1;       // skip CLS each frame
        const float4* a = s_x + (size_t)src_row * C4 + 2 * c;
        const float4* p = clip_pos + (m % NTOK) * C4 + 2 * c;
        float4 a0 = ldcs4(a), a1 = ldcs4(a + 1);
        float4 p0 = p[0], p1 = p[1];
        As[i] = cvt8(a0, a1, p0, p1);
    } else {
        int i = idx - 2 * TCH;
        if (i < WCH) {
            qw[i] = cvt8s(ldcs4(q_w + 2 * i), ldcs4(q_w + 2 * i + 1), QSCL);
        } else if (i < 3 * WCH) {
            int j = i - WCH;
            kvw[j] = cvt8s(ldcs4(kv_w + 2 * j), ldcs4(kv_w + 2 * j + 1), 1.f);
        } else if (i < 4 * WCH) {
            int j = i - 3 * WCH;
            pw[j] = cvt8s(ldcs4(proj_w + 2 * j), ldcs4(proj_w + 2 * j + 1), 1.f);
        } else if (i < 4 * WCH + DMODEL / 4) {
            int j = i - 4 * WCH;
            float4 v = q_b[j];
            v.x *= QSCL; v.y *= QSCL; v.z *= QSCL; v.w *= QSCL;
            qb2[j] = v;
        }
    }
}

// ---------------- fp16 GEMM core (R13-frozen): 256 thr, 8 warps 32x64, BK=64 -----
#define LDHB 128
#define GTILE_B (128 * LDHB)        // 16384 B
#define GSTG_B  (2 * GTILE_B)       // 32768 B
#define GSMEM   (3 * GSTG_B)        // 98304 B

// one quarter of a stage fill (2 x 16B chunks per thread)
__device__ __forceinline__ void fill_chunk_f16(uint32_t sbase, int stage,
                                               const __half* A, const __half* W,
                                               int bm, int bn, int kt, int tid, int qc) {
    uint32_t ab = sbase + stage * GSTG_B;
    uint32_t bb = ab + GTILE_B;
    #pragma unroll
    for (int it = 2 * qc; it < 2 * qc + 2; it++) {
        int c = tid + it * 256;
        int row, ch;
        if (c < 1024) {
            row = c >> 3; ch = c & 7;
            const __half* g = A + (size_t)(bm * 128 + row) * DMODEL + kt * 64 + ch * 8;
            cp16(ab + (row << 7) + (((uint32_t)(ch ^ (row & 7))) << 4), g);
        } else {
            int c2 = c - 1024;
            row = c2 >> 3; ch = c2 & 7;
            const __half* g = W + (size_t)(bn * 128 + row) * DMODEL + kt * 64 + ch * 8;
            cp16(bb + (row << 7) + (((uint32_t)(ch ^ (row & 7))) << 4), g);
        }
    }
}

template <bool HALF_OUT>
__device__ __forceinline__ void gemm_core(const __half* __restrict__ A,
                                          const __half* __restrict__ W,
                                          const float* __restrict__ bias,
                                          void* __restrict__ Cout,
                                          int Ncols, int bn, int bm,
                                          uint32_t sbase) {
    const int tid  = threadIdx.x;
    const int lane = tid & 31;
    const int w    = tid >> 5;
    const int wm   = (w & 3) * 32;
    const int wn   = (w >> 2) * 64;
    const int gr   = lane >> 2;
    const int tg   = lane & 3;
    const int lr   = lane & 15;
    const int lh   = lane >> 4;
    const uint32_t sw = (uint32_t)(lr & 7);

    uint32_t arow[2], brow[4];
    #pragma unroll
    for (int i = 0; i < 2; i++)  arow[i] = (uint32_t)(wm + i * 16 + lr) << 7;
    #pragma unroll
    for (int jb = 0; jb < 4; jb++) brow[jb] = (uint32_t)(wn + jb * 16 + lr) << 7;

    float acc[2][8][4];
    #pragma unroll
    for (int i = 0; i < 2; i++)
        #pragma unroll
        for (int j = 0; j < 8; j++)
            #pragma unroll
            for (int r = 0; r < 4; r++) acc[i][j][r] = 0.f;

    #pragma unroll
    for (int pk = 0; pk < 2; pk++) {
        #pragma unroll
        for (int qc = 0; qc < 4; qc++)
            fill_chunk_f16(sbase, pk, A, W, bm, bn, pk, tid, qc);
        asm volatile("cp.async.commit_group;\n" ::: "memory");
    }

    for (int kt = 0; kt < 12; kt++) {
        if (kt < 11) asm volatile("cp.async.wait_group 1;\n" ::: "memory");
        else         asm volatile("cp.async.wait_group 0;\n" ::: "memory");
        __syncthreads();

        const bool do_fill = (kt + 2 < 12);
        const int fstage = (kt + 2) % 3;

        const uint32_t sAs = sbase + (uint32_t)((kt % 3) * GSTG_B);
        const uint32_t sBs = sAs + GTILE_B;

        #pragma unroll
        for (int k16 = 0; k16 < 4; k16++) {
            // spread next-stage fill across the iteration (crossbar smoothing)
            if (do_fill)
                fill_chunk_f16(sbase, fstage, A, W, bm, bn, kt + 2, tid, k16);

            const uint32_t pc = (((uint32_t)(2 * k16 + lh)) ^ sw) << 4;
            uint32_t a[2][4], bb[4][4];
            #pragma unroll
            for (int i = 0; i < 2; i++)
                ldsm4(sAs + arow[i] + pc, a[i]);
            #pragma unroll
            for (int jb = 0; jb < 4; jb++)
                ldsm4(sBs + brow[jb] + pc, bb[jb]);
            #pragma unroll
            for (int i = 0; i < 2; i++)
                #pragma unroll
                for (int j = 0; j < 8; j++) {
                    uint32_t bfrag[2];
                    bfrag[0] = bb[j >> 1][(j & 1)];
                    bfrag[1] = bb[j >> 1][(j & 1) + 2];
                    mma16(acc[i][j], a[i], bfrag);
                }
        }
        if (do_fill)
            asm volatile("cp.async.commit_group;\n" ::: "memory");
    }

    #pragma unroll
    for (int i = 0; i < 2; i++) {
        #pragma unroll
        for (int j = 0; j < 8; j++) {
            int row0 = bm * 128 + wm + i * 16 + gr;
            int col  = bn * 128 + wn + j * 8 + tg * 2;
            float b0 = bias[col], b1 = bias[col + 1];
            if (HALF_OUT) {
                __half* Ch = (__half*)Cout;
                *(__half2*)(Ch + (size_t)row0 * Ncols + col) =
                    __floats2half2_rn(acc[i][j][0] + b0, acc[i][j][1] + b1);
                *(__half2*)(Ch + (size_t)(row0 + 8) * Ncols + col) =
                    __floats2half2_rn(acc[i][j][2] + b0, acc[i][j][3] + b1);
            } else {
                float* Cf = (float*)Cout;
                float* p0 = Cf + (size_t)row0 * Ncols + col;
                float* p1 = Cf + (size_t)(row0 + 8) * Ncols + col;
                p0[0] = acc[i][j][0] + b0;
                p0[1] = acc[i][j][1] + b1;
                p1[0] = acc[i][j][2] + b0;
                p1[1] = acc[i][j][3] + b1;
            }
        }
    }
}

// fused q+kv projection: bn<6 -> q GEMM, else kv GEMM
__global__ __launch_bounds__(256, 2)
void gemm_qkv_kernel(const __half* __restrict__ At, const __half* __restrict__ qw,
                     const float* __restrict__ qb2, __half* __restrict__ qh,
                     const __half* __restrict__ As, const __half* __restrict__ kvw,
                     const float* __restrict__ kv_b, __half* __restrict__ kvh) {
    extern __shared__ __half sh[];
    const uint32_t sbase = (uint32_t)__cvta_generic_to_shared(sh);
    if (blockIdx.x < 6)
        gemm_core<true>(At, qw, qb2, qh, DMODEL, blockIdx.x, blockIdx.y, sbase);
    else
        gemm_core<true>(As, kvw, kv_b, kvh, 2 * DMODEL, blockIdx.x - 6, blockIdx.y, sbase);
}

__global__ __launch_bounds__(256, 2)
void gemm_proj_kernel(const __half* __restrict__ A, const __half* __restrict__ W,
                      const float* __restrict__ bias, float* __restrict__ C) {
    extern __shared__ __half sh[];
    const uint32_t sbase = (uint32_t)__cvta_generic_to_shared(sh);
    gemm_core<false>(A, W, bias, C, DMODEL, blockIdx.x, blockIdx.y, sbase);
}

// ---------------- fp16 flash attention: 2 CTAs per (bt,h), 7 warps x 16 q-rows ----
#define ATW 224
#define AQH 112
#define AKV 224
#define SK_OFF (AQH * 128)               // 14336
#define SV_OFF (SK_OFF + AKV * 128)      // 43008
#define ASMEM (SV_OFF + AKV * 128)       // 71680 B

__global__ __launch_bounds__(ATW, 3)
void attn_mma_kernel(const __half* __restrict__ q, const __half* __restrict__ kv,
                     __half* __restrict__ o) {
    extern __shared__ __half smh[];
    const uint32_t sbase = (uint32_t)__cvta_generic_to_shared(smh);
    const uint32_t sQa = sbase;
    const uint32_t sKa = sbase + SK_OFF;
    const uint32_t sVa = sbase + SV_OFF;

    const int b2   = blockIdx.x;
    const int bt   = b2 / (2 * NHEAD);
    const int r2   = b2 - bt * (2 * NHEAD);
    const int h    = r2 >> 1;
    const int half = r2 & 1;
    const int tid  = threadIdx.x;
    const int lane = tid & 31;
    const int w    = tid >> 5;        // 0..6
    const int gr   = lane >> 2;
    const int tg   = lane & 3;
    const int lr   = lane & 15;
    const int lh   = lane >> 4;
    const uint32_t sw = (uint32_t)(lr & 7);

    // ---- stage Q (112 rows) + K (224 rows): commit group 0 ----
    for (int idx = tid; idx < AQH * 8; idx += ATW) {
        int r = idx >> 3, ch = idx & 7;
        int grow = half * AQH + r;
        int sz = (grow < NTOK) ? 16 : 0;
        int rr = (grow < NTOK) ? grow : 0;
        uint32_t soff = ((uint32_t)r << 7) + (((uint32_t)(ch ^ (r & 7))) << 4);
        cp16z(sQa + soff, q + ((size_t)bt * NTOK + rr) * DMODEL + h * HDIM + ch * 8, sz);
    }
    for (int idx = tid; idx < AKV * 8; idx += ATW) {
        int r = idx >> 3, ch = idx & 7;
        int sz = (r < NTOK) ? 16 : 0;
        int rr = (r < NTOK) ? r : 0;
        uint32_t soff = ((uint32_t)r << 7) + (((uint32_t)(ch ^ (r & 7))) << 4);
        cp16z(sKa + soff, kv + ((size_t)bt * NTOK + rr) * (2 * DMODEL) + h * HDIM + ch * 8, sz);
    }
    asm volatile("cp.async.commit_group;\n" ::: "memory");

    // ---- stage V (224 rows): commit group 1 ----
    for (int idx = tid; idx < AKV * 8; idx += ATW) {
        int r = idx >> 3, ch = idx & 7;
        int sz = (r < NTOK) ? 16 : 0;
        int rr = (r < NTOK) ? r : 0;
        uint32_t soff = ((uint32_t)r << 7) + (((uint32_t)(ch ^ (r & 7))) << 4);
        cp16z(sVa + soff, kv + ((size_t)bt * NTOK + rr) * (2 * DMODEL) + DMODEL + h * HDIM + ch * 8, sz);
    }
    asm volatile("cp.async.commit_group;\n" ::: "memory");

    // wait for Q+K only; V drains behind the first S tile
    asm volatile("cp.async.wait_group 1;\n" ::: "memory");
    __syncthreads();

    // ---- preload Q A-fragments (16 rows per warp, 4 k16 chunks) ----
    const int qb = w * 16;
    const uint32_t qrow = (uint32_t)(qb + lr) << 7;
    uint32_t qa[4][4];
    #pragma unroll
    for (int kk = 0; kk < 4; kk++)
        ldsm4(sQa + qrow + ((((uint32_t)(2 * kk + lh)) ^ sw) << 4), qa[kk]);

    float oacc[8][4];
    #pragma unroll
    for (int n = 0; n < 8; n++)
        #pragma unroll
        for (int r = 0; r < 4; r++) oacc[n][r] = 0.f;
    float lsum[2] = {0.f, 0.f};

    // ---- first S tile (kt=0) overlaps V staging ----
    bool v_waited = false;

    for (int kt = 0; kt < 7; kt++) {
        float s[4][4];
        #pragma unroll
        for (int j = 0; j < 4; j++)
            #pragma unroll
            for (int r = 0; r < 4; r++) s[j][r] = 0.f;

        #pragma unroll
        for (int kk = 0; kk < 4; kk++) {
            const uint32_t pc = (((uint32_t)(2 * kk + lh)) ^ sw) << 4;
            uint32_t kb[2][4];
            #pragma unroll
            for (int jb = 0; jb < 2; jb++)
                ldsm4(sKa + (((uint32_t)(kt * 32 + jb * 16 + lr)) << 7) + pc, kb[jb]);
            #pragma unroll
            for (int j = 0; j < 4; j++) {
                uint32_t bfrag[2];
                bfrag[0] = kb[j >> 1][(j & 1)];
                bfrag[1] = kb[j >> 1][(j & 1) + 2];
                mma16(s[j], qa[kk], bfrag);
            }
        }

        if (kt == 6) {
            #pragma unroll
            for (int j = 0; j < 4; j++) {
                int c0 = 192 + j * 8 + 2 * tg;
                if (c0 >= NTOK)     { s[j][0] = s[j][2] = -1e30f; }
                if (c0 + 1 >= NTOK) { s[j][1] = s[j][3] = -1e30f; }
            }
        }

        if (!v_waited) {
            asm volatile("cp.async.wait_group 0;\n" ::: "memory");
            __syncthreads();
            v_waited = true;
        }

        #pragma unroll
        for (int ck = 0; ck < 2; ck++) {
            uint32_t pa[4];
            int j0 = ck * 2;
            pa[0] = pack2h(s[j0][0],     s[j0][1]);
            pa[1] = pack2h(s[j0][2],     s[j0][3]);
            pa[2] = pack2h(s[j0 + 1][0], s[j0 + 1][1]);
            pa[3] = pack2h(s[j0 + 1][2], s[j0 + 1][3]);
            ex2x2(pa[0]); ex2x2(pa[1]); ex2x2(pa[2]); ex2x2(pa[3]);

            float2 f0 = h22f2(pa[0]), f2 = h22f2(pa[2]);
            lsum[0] += (f0.x + f0.y) + (f2.x + f2.y);
            float2 f1 = h22f2(pa[1]), f3 = h22f2(pa[3]);
            lsum[1] += (f1.x + f1.y) + (f3.x + f3.y);

            int kr = kt * 32 + ck * 16;
            uint32_t vbb[4][4];
            #pragma unroll
            for (int nb = 0; nb < 4; nb++)
                ldsm4t(sVa + (((uint32_t)(kr + lr)) << 7) +
                       ((((uint32_t)(2 * nb + lh)) ^ sw) << 4), vbb[nb]);

            #pragma unroll
            for (int n = 0; n < 8; n++) {
                uint32_t vb[2];
                vb[0] = vbb[n >> 1][(n & 1) * 2];
                vb[1] = vbb[n >> 1][(n & 1) * 2 + 1];
                mma16(oacc[n], pa, vb);
            }
        }
    }

    #pragma unroll
    for (int hl = 0; hl < 2; hl++) {
        lsum[hl] += __shfl_xor_sync(0xffffffffu, lsum[hl], 1);
        lsum[hl] += __shfl_xor_sync(0xffffffffu, lsum[hl], 2);
    }

    #pragma unroll
    for (int hl = 0; hl < 2; hl++) {
        float inv = 1.f / lsum[hl];
        int row = half * AQH + qb + gr + 8 * hl;
        if (row < NTOK) {
            __half* dst = o + ((size_t)bt * NTOK + row) * DMODEL + h * HDIM;
            #pragma unroll
            for (int n = 0; n < 8; n++) {
                *(__half2*)(dst + n * 8 + 2 * tg) =
                    __floats2half2_rn(oacc[n][2 * hl] * inv, oacc[n][2 * hl + 1] * inv);
            }
        }
    }
}

// ---------------- launch ----------------
extern "C" void kernel_launch(void* const* d_in, const int* in_sizes, int n_in,
                              void* d_out, int out_size) {
    const float* s_x      = (const float*)d_in[0];
    const float* t_x      = (const float*)d_in[1];
    const float* clip_pos = (const float*)d_in[2];
    const float* vmae_pos = (const float*)d_in[3];
    const float* q_w      = (const float*)d_in[4];
    const float* q_b      = (const float*)d_in[5];
    const float* kv_w     = (const float*)d_in[6];
    const float* kv_b     = (const float*)d_in[7];
    const float* proj_w   = (const float*)d_in[8];
    const float* proj_b   = (const float*)d_in[9];
    float* out = (float*)d_out;
    (void)in_sizes; (void)n_in; (void)out_size;

    __half *At, *As_, *qh, *kvh, *ob, *qw, *kvw, *pw;
    float *qb2;
    cudaGetSymbolAddress((void**)&At,  g_At);
    cudaGetSymbolAddress((void**)&As_, g_As);
    cudaGetSymbolAddress((void**)&qh,  g_q);
    cudaGetSymbolAddress((void**)&kvh, g_kv);
    cudaGetSymbolAddress((void**)&ob,  g_o);
    cudaGetSymbolAddress((void**)&qw,  g_qw);
    cudaGetSymbolAddress((void**)&kvw, g_kvw);
    cudaGetSymbolAddress((void**)&pw,  g_pw);
    cudaGetSymbolAddress((void**)&qb2, g_qb2);

    cudaFuncSetAttribute(gemm_qkv_kernel,  cudaFuncAttributeMaxDynamicSharedMemorySize, GSMEM);
    cudaFuncSetAttribute(gemm_proj_kernel, cudaFuncAttributeMaxDynamicSharedMemorySize, GSMEM);
    cudaFuncSetAttribute(attn_mma_kernel,  cudaFuncAttributeMaxDynamicSharedMemorySize, ASMEM);

    prepconv_kernel<<<(PC_TOTAL + 255) / 256, 256>>>(
        (const float4*)t_x, (const float4*)s_x,
        (const float4*)vmae_pos, (const float4*)clip_pos,
        (const float4*)q_w, (const float4*)kv_w, (const float4*)proj_w,
        (const float4*)q_b,
        (uint4*)At, (uint4*)As_, (uint4*)qw, (uint4*)kvw, (uint4*)pw,
        (float4*)qb2);

    gemm_qkv_kernel<<<dim3(18, MROWS / 128), 256, GSMEM>>>(
        At, qw, qb2, qh, As_, kvw, kv_b, kvh);

    attn_mma_kernel<<<BT * NHEAD * 2, ATW, ASMEM>>>(qh, kvh, ob);

    gemm_proj_kernel<<<dim3(DMODEL / 128, MROWS / 128), 256, GSMEM>>>(ob, pw, proj_b, out);
}

// round 16
// speedup vs baseline: 1.0346x; 1.0231x over previous
#include <cuda_runtime.h>
#include <cuda_fp16.h>
#include <cstdint>

// ---------------- problem constants ----------------
#define BT    128
#define NTOK  196
#define DMODEL 768
#define NHEAD 12
#define HDIM  64
#define MROWS (BT * NTOK)      // 25088
#define HROWS (MROWS / 2)      // 12544 (= 98 * 128)
#define ATT_SCALE 0.125f
#define LOG2E 1.44269504088896f

// ---------------- scratch ----------------
__device__ __half g_At[(size_t)MROWS * DMODEL];
__device__ __half g_As[(size_t)MROWS * DMODEL];
__device__ __half g_q [(size_t)MROWS * DMODEL];
__device__ __half g_kv[(size_t)MROWS * 2 * DMODEL];
__device__ __half g_o [(size_t)MROWS * DMODEL];
__device__ __half g_qw [DMODEL * DMODEL];
__device__ __half g_kvw[2 * DMODEL * DMODEL];
__device__ __half g_pw [DMODEL * DMODEL];
__device__ float  g_qb2[DMODEL];

// ---------------- helpers ----------------
__device__ __forceinline__ void mma16(float* c, const uint32_t* a, const uint32_t* b) {
    asm volatile(
        "mma.sync.aligned.m16n8k16.row.col.f32.f16.f16.f32 "
        "{%0,%1,%2,%3}, {%4,%5,%6,%7}, {%8,%9}, {%0,%1,%2,%3};\n"
        : "+f"(c[0]), "+f"(c[1]), "+f"(c[2]), "+f"(c[3])
        : "r"(a[0]), "r"(a[1]), "r"(a[2]), "r"(a[3]), "r"(b[0]), "r"(b[1]));
}

__device__ __forceinline__ void ldsm4(uint32_t saddr, uint32_t* r) {
    asm volatile("ldmatrix.sync.aligned.m8n8.x4.shared.b16 {%0,%1,%2,%3}, [%4];"
                 : "=r"(r[0]), "=r"(r[1]), "=r"(r[2]), "=r"(r[3]) : "r"(saddr));
}

__device__ __forceinline__ void ldsm4t(uint32_t saddr, uint32_t* r) {
    asm volatile("ldmatrix.sync.aligned.m8n8.x4.trans.shared.b16 {%0,%1,%2,%3}, [%4];"
                 : "=r"(r[0]), "=r"(r[1]), "=r"(r[2]), "=r"(r[3]) : "r"(saddr));
}

__device__ __forceinline__ void cp16(uint32_t saddr, const void* gptr) {
    asm volatile("cp.async.cg.shared.global [%0], [%1], 16;\n"
                 :: "r"(saddr), "l"(gptr) : "memory");
}

__device__ __forceinline__ void cp16z(uint32_t saddr, const void* gptr, int src_bytes) {
    asm volatile("cp.async.cg.shared.global [%0], [%1], 16, %2;\n"
                 :: "r"(saddr), "l"(gptr), "r"(src_bytes) : "memory");
}

__device__ __forceinline__ uint32_t pack2h(float a, float b) {
    __half2 h = __floats2half2_rn(a, b);
    return *(uint32_t*)&h;
}

__device__ __forceinline__ void ex2x2(uint32_t& x) {
    asm volatile("ex2.approx.f16x2 %0, %0;" : "+r"(x));
}

__device__ __forceinline__ float2 h22f2(uint32_t x) {
    return __half22float2(*(__half2*)&x);
}

__device__ __forceinline__ float4 ldcs4(const float4* p) {
    return __ldcs(p);
}

// ---------------- weight conversion (qw*S*log2e, kvw, pw, q_b) -----------------
#define C4 (DMODEL / 4)
#define C8 (DMODEL / 8)
#define WN4 (DMODEL * DMODEL / 4)
#define WCH (WN4 / 2)
#define QSCL (ATT_SCALE * LOG2E)
#define CW_TOTAL (4 * WCH + DMODEL / 4)

__device__ __forceinline__ uint4 cvt8(float4 a0, float4 a1, float4 p0, float4 p1) {
    uint4 o;
    o.x = pack2h(a0.x + p0.x, a0.y + p0.y);
    o.y = pack2h(a0.z + p0.z, a0.w + p0.w);
    o.z = pack2h(a1.x + p1.x, a1.y + p1.y);
    o.w = pack2h(a1.z + p1.z, a1.w + p1.w);
    return o;
}

__device__ __forceinline__ uint4 cvt8s(float4 a0, float4 a1, float s) {
    uint4 o;
    o.x = pack2h(a0.x * s, a0.y * s);
    o.y = pack2h(a0.z * s, a0.w * s);
    o.z = pack2h(a1.x * s, a1.y * s);
    o.w = pack2h(a1.z * s, a1.w * s);
    return o;
}

__global__ void conv_w_kernel(const float4* __restrict__ q_w,
                              const float4* __restrict__ kv_w,
                              const float4* __restrict__ proj_w,
                              const float4* __restrict__ q_b,
                              uint4* __restrict__ qw, uint4* __restrict__ kvw,
                              uint4* __restrict__ pw, float4* __restrict__ qb2) {
    int i = blockIdx.x * blockDim.x + threadIdx.x;
    if (i < WCH) {
        qw[i] = cvt8s(ldcs4(q_w + 2 * i), ldcs4(q_w + 2 * i + 1), QSCL);
    } else if (i < 3 * WCH) {
        int j = i - WCH;
        kvw[j] = cvt8s(ldcs4(kv_w + 2 * j), ldcs4(kv_w + 2 * j + 1), 1.f);
    } else if (i < 4 * WCH) {
        int j = i - 3 * WCH;
        pw[j] = cvt8s(ldcs4(proj_w + 2 * j), ldcs4(proj_w + 2 * j + 1), 1.f);
    } else if (i < CW_TOTAL) {
        int j = i - 4 * WCH;
        float4 v = q_b[j];
        v.x *= QSCL; v.y *= QSCL; v.z *= QSCL; v.w *= QSCL;
        qb2[j] = v;
    }
}

// ---------------- activation prep for one bt-half (rows [m0, m0+HROWS)) --------
#define HTCH (HROWS * C8)               // 1204224 chunks per path per half
#define PA_TOTAL (2 * HTCH)

__global__ void prep_act_kernel(const float4* __restrict__ t_x,
                                const float4* __restrict__ s_x,
                                const float4* __restrict__ vmae_pos,
                                const float4* __restrict__ clip_pos,
                                uint4* __restrict__ At, uint4* __restrict__ As,
                                int m0) {
    int idx = blockIdx.x * blockDim.x + threadIdx.x;
    if (idx < HTCH) {
        int m = m0 + idx / C8;
        int c = idx - (idx / C8) * C8;
        const float4* a = t_x + (size_t)m * C4 + 2 * c;
        const float4* p = vmae_pos + (m % NTOK) * C4 + 2 * c;
        float4 a0 = ldcs4(a), a1 = ldcs4(a + 1);
        float4 p0 = p[0], p1 = p[1];
        At[(size_t)m * C8 + c] = cvt8(a0, a1, p0, p1);
    } else if (idx < 2 * HTCH) {
        int i = idx - HTCH;
        int m = m0 + i / C8;
        int c = i - (i / C8) * C8;
        int src_row = m + m / NTOK + 1;       // skip CLS each frame
        const float4* a = s_x + (size_t)src_row * C4 + 2 * c;
        const float4* p = clip_pos + (m % NTOK) * C4 + 2 * c;
        float4 a0 = ldcs4(a), a1 = ldcs4(a + 1);
        float4 p0 = p[0], p1 = p[1];
        As[(size_t)m * C8 + c] = cvt8(a0, a1, p0, p1);
    }
}

// ---------------- fp16 GEMM core (frozen): 256 thr, 8 warps 32x64, BK=64 --------
#define LDHB 128
#define GTILE_B (128 * LDHB)        // 16384 B
#define GSTG_B  (2 * GTILE_B)       // 32768 B
#define GSMEM   (3 * GSTG_B)        // 98304 B

__device__ __forceinline__ void fill_chunk_f16(uint32_t sbase, int stage,
                                               const __half* A, const __half* W,
                                               int bm, int bn, int kt, int tid, int qc) {
    uint32_t ab = sbase + stage * GSTG_B;
    uint32_t bb = ab + GTILE_B;
    #pragma unroll
    for (int it = 2 * qc; it < 2 * qc + 2; it++) {
        int c = tid + it * 256;
        int row, ch;
        if (c < 1024) {
            row = c >> 3; ch = c & 7;
            const __half* g = A + (size_t)(bm * 128 + row) * DMODEL + kt * 64 + ch * 8;
            cp16(ab + (row << 7) + (((uint32_t)(ch ^ (row & 7))) << 4), g);
        } else {
            int c2 = c - 1024;
            row = c2 >> 3; ch = c2 & 7;
            const __half* g = W + (size_t)(bn * 128 + row) * DMODEL + kt * 64 + ch * 8;
            cp16(bb + (row << 7) + (((uint32_t)(ch ^ (row & 7))) << 4), g);
        }
    }
}

template <bool HALF_OUT>
__device__ __forceinline__ void gemm_core(const __half* __restrict__ A,
                                          const __half* __restrict__ W,
                                          const float* __restrict__ bias,
                                          void* __restrict__ Cout,
                                          int Ncols, int bn, int bm,
                                          uint32_t sbase) {
    const int tid  = threadIdx.x;
    const int lane = tid & 31;
    const int w    = tid >> 5;
    const int wm   = (w & 3) * 32;
    const int wn   = (w >> 2) * 64;
    const int gr   = lane >> 2;
    const int tg   = lane & 3;
    const int lr   = lane & 15;
    const int lh   = lane >> 4;
    const uint32_t sw = (uint32_t)(lr & 7);

    uint32_t arow[2], brow[4];
    #pragma unroll
    for (int i = 0; i < 2; i++)  arow[i] = (uint32_t)(wm + i * 16 + lr) << 7;
    #pragma unroll
    for (int jb = 0; jb < 4; jb++) brow[jb] = (uint32_t)(wn + jb * 16 + lr) << 7;

    float acc[2][8][4];
    #pragma unroll
    for (int i = 0; i < 2; i++)
        #pragma unroll
        for (int j = 0; j < 8; j++)
            #pragma unroll
            for (int r = 0; r < 4; r++) acc[i][j][r] = 0.f;

    #pragma unroll
    for (int pk = 0; pk < 2; pk++) {
        #pragma unroll
        for (int qc = 0; qc < 4; qc++)
            fill_chunk_f16(sbase, pk, A, W, bm, bn, pk, tid, qc);
        asm volatile("cp.async.commit_group;\n" ::: "memory");
    }

    for (int kt = 0; kt < 12; kt++) {
        if (kt < 11) asm volatile("cp.async.wait_group 1;\n" ::: "memory");
        else         asm volatile("cp.async.wait_group 0;\n" ::: "memory");
        __syncthreads();

        const bool do_fill = (kt + 2 < 12);
        const int fstage = (kt + 2) % 3;

        const uint32_t sAs = sbase + (uint32_t)((kt % 3) * GSTG_B);
        const uint32_t sBs = sAs + GTILE_B;

        #pragma unroll
        for (int k16 = 0; k16 < 4; k16++) {
            if (do_fill)
                fill_chunk_f16(sbase, fstage, A, W, bm, bn, kt + 2, tid, k16);

            const uint32_t pc = (((uint32_t)(2 * k16 + lh)) ^ sw) << 4;
            uint32_t a[2][4], bb[4][4];
            #pragma unroll
            for (int i = 0; i < 2; i++)
                ldsm4(sAs + arow[i] + pc, a[i]);
            #pragma unroll
            for (int jb = 0; jb < 4; jb++)
                ldsm4(sBs + brow[jb] + pc, bb[jb]);
            #pragma unroll
            for (int i = 0; i < 2; i++)
                #pragma unroll
                for (int j = 0; j < 8; j++) {
                    uint32_t bfrag[2];
                    bfrag[0] = bb[j >> 1][(j & 1)];
                    bfrag[1] = bb[j >> 1][(j & 1) + 2];
                    mma16(acc[i][j], a[i], bfrag);
                }
        }
        if (do_fill)
            asm volatile("cp.async.commit_group;\n" ::: "memory");
    }

    #pragma unroll
    for (int i = 0; i < 2; i++) {
        #pragma unroll
        for (int j = 0; j < 8; j++) {
            int row0 = bm * 128 + wm + i * 16 + gr;
            int col  = bn * 128 + wn + j * 8 + tg * 2;
            float b0 = bias[col], b1 = bias[col + 1];
            if (HALF_OUT) {
                __half* Ch = (__half*)Cout;
                *(__half2*)(Ch + (size_t)row0 * Ncols + col) =
                    __floats2half2_rn(acc[i][j][0] + b0, acc[i][j][1] + b1);
                *(__half2*)(Ch + (size_t)(row0 + 8) * Ncols + col) =
                    __floats2half2_rn(acc[i][j][2] + b0, acc[i][j][3] + b1);
            } else {
                float* Cf = (float*)Cout;
                float* p0 = Cf + (size_t)row0 * Ncols + col;
                float* p1 = Cf + (size_t)(row0 + 8) * Ncols + col;
                p0[0] = acc[i][j][0] + b0;
                p0[1] = acc[i][j][1] + b1;
                p1[0] = acc[i][j][2] + b0;
                p1[1] = acc[i][j][3] + b1;
            }
        }
    }
}

// fused q+kv projection for one bt-half: bn<6 -> q GEMM, else kv GEMM
__global__ __launch_bounds__(256, 2)
void gemm_qkv_kernel(const __half* __restrict__ At, const __half* __restrict__ qw,
                     const float* __restrict__ qb2, __half* __restrict__ qh,
                     const __half* __restrict__ As, const __half* __restrict__ kvw,
                     const float* __restrict__ kv_b, __half* __restrict__ kvh,
                     int bm_base) {
    extern __shared__ __half sh[];
    const uint32_t sbase = (uint32_t)__cvta_generic_to_shared(sh);
    int bm = bm_base + blockIdx.y;
    if (blockIdx.x < 6)
        gemm_core<true>(At, qw, qb2, qh, DMODEL, blockIdx.x, bm, sbase);
    else
        gemm_core<true>(As, kvw, kv_b, kvh, 2 * DMODEL, blockIdx.x - 6, bm, sbase);
}

__global__ __launch_bounds__(256, 2)
void gemm_proj_kernel(const __half* __restrict__ A, const __half* __restrict__ W,
                      const float* __restrict__ bias, float* __restrict__ C,
                      int bm_base) {
    extern __shared__ __half sh[];
    const uint32_t sbase = (uint32_t)__cvta_generic_to_shared(sh);
    gemm_core<false>(A, W, bias, C, DMODEL, blockIdx.x, bm_base + blockIdx.y, sbase);
}

// ---------------- fp16 flash attention: 2 CTAs per (bt,h), 7 warps x 16 q-rows ----
#define ATW 224
#define AQH 112
#define AKV 224
#define SK_OFF (AQH * 128)               // 14336
#define SV_OFF (SK_OFF + AKV * 128)      // 43008
#define ASMEM (SV_OFF + AKV * 128)       // 71680 B

__global__ __launch_bounds__(ATW, 3)
void attn_mma_kernel(const __half* __restrict__ q, const __half* __restrict__ kv,
                     __half* __restrict__ o, int bt_base) {
    extern __shared__ __half smh[];
    const uint32_t sbase = (uint32_t)__cvta_generic_to_shared(smh);
    const uint32_t sQa = sbase;
    const uint32_t sKa = sbase + SK_OFF;
    const uint32_t sVa = sbase + SV_OFF;

    const int b2   = blockIdx.x;
    const int bt   = bt_base + b2 / (2 * NHEAD);
    const int r2   = b2 % (2 * NHEAD);
    const int h    = r2 >> 1;
    const int half = r2 & 1;
    const int tid  = threadIdx.x;
    const int lane = tid & 31;
    const int w    = tid >> 5;        // 0..6
    const int gr   = lane >> 2;
    const int tg   = lane & 3;
    const int lr   = lane & 15;
    const int lh   = lane >> 4;
    const uint32_t sw = (uint32_t)(lr & 7);

    // ---- stage Q (112 rows) + K (224 rows): commit group 0 ----
    for (int idx = tid; idx < AQH * 8; idx += ATW) {
        int r = idx >> 3, ch = idx & 7;
        int grow = half * AQH + r;
        int sz = (grow < NTOK) ? 16 : 0;
        int rr = (grow < NTOK) ? grow : 0;
        uint32_t soff = ((uint32_t)r << 7) + (((uint32_t)(ch ^ (r & 7))) << 4);
        cp16z(sQa + soff, q + ((size_t)bt * NTOK + rr) * DMODEL + h * HDIM + ch * 8, sz);
    }
    for (int idx = tid; idx < AKV * 8; idx += ATW) {
        int r = idx >> 3, ch = idx & 7;
        int sz = (r < NTOK) ? 16 : 0;
        int rr = (r < NTOK) ? r : 0;
        uint32_t soff = ((uint32_t)r << 7) + (((uint32_t)(ch ^ (r & 7))) << 4);
        cp16z(sKa + soff, kv + ((size_t)bt * NTOK + rr) * (2 * DMODEL) + h * HDIM + ch * 8, sz);
    }
    asm volatile("cp.async.commit_group;\n" ::: "memory");

    // ---- stage V (224 rows): commit group 1 ----
    for (int idx = tid; idx < AKV * 8; idx += ATW) {
        int r = idx >> 3, ch = idx & 7;
        int sz = (r < NTOK) ? 16 : 0;
        int rr = (r < NTOK) ? r : 0;
        uint32_t soff = ((uint32_t)r << 7) + (((uint32_t)(ch ^ (r & 7))) << 4);
        cp16z(sVa + soff, kv + ((size_t)bt * NTOK + rr) * (2 * DMODEL) + DMODEL + h * HDIM + ch * 8, sz);
    }
    asm volatile("cp.async.commit_group;\n" ::: "memory");

    asm volatile("cp.async.wait_group 1;\n" ::: "memory");
    __syncthreads();

    // ---- preload Q A-fragments (16 rows per warp, 4 k16 chunks) ----
    const int qb = w * 16;
    const uint32_t qrow = (uint32_t)(qb + lr) << 7;
    uint32_t qa[4][4];
    #pragma unroll
    for (int kk = 0; kk < 4; kk++)
        ldsm4(sQa + qrow + ((((uint32_t)(2 * kk + lh)) ^ sw) << 4), qa[kk]);

    float oacc[8][4];
    #pragma unroll
    for (int n = 0; n < 8; n++)
        #pragma unroll
        for (int r = 0; r < 4; r++) oacc[n][r] = 0.f;
    float lsum[2] = {0.f, 0.f};

    bool v_waited = false;

    for (int kt = 0; kt < 7; kt++) {
        float s[4][4];
        #pragma unroll
        for (int j = 0; j < 4; j++)
            #pragma unroll
            for (int r = 0; r < 4; r++) s[j][r] = 0.f;

        #pragma unroll
        for (int kk = 0; kk < 4; kk++) {
            const uint32_t pc = (((uint32_t)(2 * kk + lh)) ^ sw) << 4;
            uint32_t kb[2][4];
            #pragma unroll
            for (int jb = 0; jb < 2; jb++)
                ldsm4(sKa + (((uint32_t)(kt * 32 + jb * 16 + lr)) << 7) + pc, kb[jb]);
            #pragma unroll
            for (int j = 0; j < 4; j++) {
                uint32_t bfrag[2];
                bfrag[0] = kb[j >> 1][(j & 1)];
                bfrag[1] = kb[j >> 1][(j & 1) + 2];
                mma16(s[j], qa[kk], bfrag);
            }
        }

        if (kt == 6) {
            #pragma unroll
            for (int j = 0; j < 4; j++) {
                int c0 = 192 + j * 8 + 2 * tg;
                if (c0 >= NTOK)     { s[j][0] = s[j][2] = -1e30f; }
                if (c0 + 1 >= NTOK) { s[j][1] = s[j][3] = -1e30f; }
            }
        }

        if (!v_waited) {
            asm volatile("cp.async.wait_group 0;\n" ::: "memory");
            __syncthreads();
            v_waited = true;
        }

        #pragma unroll
        for (int ck = 0; ck < 2; ck++) {
            uint32_t pa[4];
            int j0 = ck * 2;
            pa[0] = pack2h(s[j0][0],     s[j0][1]);
            pa[1] = pack2h(s[j0][2],     s[j0][3]);
            pa[2] = pack2h(s[j0 + 1][0], s[j0 + 1][1]);
            pa[3] = pack2h(s[j0 + 1][2], s[j0 + 1][3]);
            ex2x2(pa[0]); ex2x2(pa[1]); ex2x2(pa[2]); ex2x2(pa[3]);

            float2 f0 = h22f2(pa[0]), f2 = h22f2(pa[2]);
            lsum[0] += (f0.x + f0.y) + (f2.x + f2.y);
            float2 f1 = h22f2(pa[1]), f3 = h22f2(pa[3]);
            lsum[1] += (f1.x + f1.y) + (f3.x + f3.y);

            int kr = kt * 32 + ck * 16;
            uint32_t vbb[4][4];
            #pragma unroll
            for (int nb = 0; nb < 4; nb++)
                ldsm4t(sVa + (((uint32_t)(kr + lr)) << 7) +
                       ((((uint32_t)(2 * nb + lh)) ^ sw) << 4), vbb[nb]);

            #pragma unroll
            for (int n = 0; n < 8; n++) {
                uint32_t vb[2];
                vb[0] = vbb[n >> 1][(n & 1) * 2];
                vb[1] = vbb[n >> 1][(n & 1) * 2 + 1];
                mma16(oacc[n], pa, vb);
            }
        }
    }

    #pragma unroll
    for (int hl = 0; hl < 2; hl++) {
        lsum[hl] += __shfl_xor_sync(0xffffffffu, lsum[hl], 1);
        lsum[hl] += __shfl_xor_sync(0xffffffffu, lsum[hl], 2);
    }

    #pragma unroll
    for (int hl = 0; hl < 2; hl++) {
        float inv = 1.f / lsum[hl];
        int row = half * AQH + qb + gr + 8 * hl;
        if (row < NTOK) {
            __half* dst = o + ((size_t)bt * NTOK + row) * DMODEL + h * HDIM;
            #pragma unroll
            for (int n = 0; n < 8; n++) {
                *(__half2*)(dst + n * 8 + 2 * tg) =
                    __floats2half2_rn(oacc[n][2 * hl] * inv, oacc[n][2 * hl + 1] * inv);
            }
        }
    }
}

// ---------------- launch: two bt-half chains pipelined across streams ----------
extern "C" void kernel_launch(void* const* d_in, const int* in_sizes, int n_in,
                              void* d_out, int out_size) {
    const float* s_x      = (const float*)d_in[0];
    const float* t_x      = (const float*)d_in[1];
    const float* clip_pos = (const float*)d_in[2];
    const float* vmae_pos = (const float*)d_in[3];
    const float* q_w      = (const float*)d_in[4];
    const float* q_b      = (const float*)d_in[5];
    const float* kv_w     = (const float*)d_in[6];
    const float* kv_b     = (const float*)d_in[7];
    const float* proj_w   = (const float*)d_in[8];
    const float* proj_b   = (const float*)d_in[9];
    float* out = (float*)d_out;
    (void)in_sizes; (void)n_in; (void)out_size;

    __half *At, *As_, *qh, *kvh, *ob, *qw, *kvw, *pw;
    float *qb2;
    cudaGetSymbolAddress((void**)&At,  g_At);
    cudaGetSymbolAddress((void**)&As_, g_As);
    cudaGetSymbolAddress((void**)&qh,  g_q);
    cudaGetSymbolAddress((void**)&kvh, g_kv);
    cudaGetSymbolAddress((void**)&ob,  g_o);
    cudaGetSymbolAddress((void**)&qw,  g_qw);
    cudaGetSymbolAddress((void**)&kvw, g_kvw);
    cudaGetSymbolAddress((void**)&pw,  g_pw);
    cudaGetSymbolAddress((void**)&qb2, g_qb2);

    cudaFuncSetAttribute(gemm_qkv_kernel,  cudaFuncAttributeMaxDynamicSharedMemorySize, GSMEM);
    cudaFuncSetAttribute(gemm_proj_kernel, cudaFuncAttributeMaxDynamicSharedMemorySize, GSMEM);
    cudaFuncSetAttribute(attn_mma_kernel,  cudaFuncAttributeMaxDynamicSharedMemorySize, ASMEM);

    // fork resources (created each call; destroyed when not capturing)
    cudaStream_t s2;
    cudaEvent_t eP, eJ;
    cudaStreamCreateWithFlags(&s2, cudaStreamNonBlocking);
    cudaEventCreateWithFlags(&eP, cudaEventDisableTiming);
    cudaEventCreateWithFlags(&eJ, cudaEventDisableTiming);

    const int paBlocks = (PA_TOTAL + 255) / 256;

    // ---- chain L prologue: weights + prep(h0) ----
    conv_w_kernel<<<(CW_TOTAL + 255) / 256, 256>>>(
        (const float4*)q_w, (const float4*)kv_w, (const float4*)proj_w,
        (const float4*)q_b, (uint4*)qw, (uint4*)kvw, (uint4*)pw, (float4*)qb2);
    prep_act_kernel<<<paBlocks, 256>>>(
        (const float4*)t_x, (const float4*)s_x,
        (const float4*)vmae_pos, (const float4*)clip_pos,
        (uint4*)At, (uint4*)As_, 0);

    // ---- fork: s2 starts after weights + prep(h0); prep(h1) overlaps qkv(h0) ----
    cudaEventRecord(eP, 0);
    cudaStreamWaitEvent(s2, eP, 0);

    prep_act_kernel<<<paBlocks, 256, 0, s2>>>(
        (const float4*)t_x, (const float4*)s_x,
        (const float4*)vmae_pos, (const float4*)clip_pos,
        (uint4*)At, (uint4*)As_, HROWS);

    // ---- chain L: half 0 ----
    gemm_qkv_kernel<<<dim3(18, HROWS / 128), 256, GSMEM>>>(
        At, qw, qb2, qh, As_, kvw, kv_b, kvh, 0);
    attn_mma_kernel<<<(BT / 2) * NHEAD * 2, ATW, ASMEM>>>(qh, kvh, ob, 0);
    gemm_proj_kernel<<<dim3(DMODEL / 128, HROWS / 128), 256, GSMEM>>>(ob, pw, proj_b, out, 0);

    // ---- chain s2: half 1 ----
    gemm_qkv_kernel<<<dim3(18, HROWS / 128), 256, GSMEM, s2>>>(
        At, qw, qb2, qh, As_, kvw, kv_b, kvh, HROWS / 128);
    attn_mma_kernel<<<(BT / 2) * NHEAD * 2, ATW, ASMEM, s2>>>(qh, kvh, ob, BT / 2);
    gemm_proj_kernel<<<dim3(DMODEL / 128, HROWS / 128), 256, GSMEM, s2>>>(ob, pw, proj_b, out, HROWS / 128);

    // ---- join ----
    cudaEventRecord(eJ, s2);
    cudaStreamWaitEvent(0, eJ, 0);

    // destroy fork resources only outside capture (during capture the graph
    // retains the dependencies; destroying mid-capture would invalidate it)
    cudaStreamCaptureStatus st = cudaStreamCaptureStatusNone;
    cudaError_t qerr = cudaStreamIsCapturing(0, &st);
    if (qerr == cudaSuccess && st == cudaStreamCaptureStatusNone) {
        cudaStreamDestroy(s2);
        cudaEventDestroy(eP);
        cudaEventDestroy(eJ);
    }
}

// round 17
// speedup vs baseline: 1.0363x; 1.0016x over previous
#include <cuda_runtime.h>
#include <cuda_fp16.h>
#include <cstdint>

// ---------------- problem constants ----------------
#define BT    128
#define NTOK  196
#define DMODEL 768
#define NHEAD 12
#define HDIM  64
#define MROWS (BT * NTOK)      // 25088
#define QROWS (MROWS / 4)      // 6272 (= 49 * 128)
#define QBT   (BT / 4)         // 32
#define ATT_SCALE 0.125f
#define LOG2E 1.44269504088896f

// ---------------- scratch ----------------
__device__ __half g_At[(size_t)MROWS * DMODEL];
__device__ __half g_As[(size_t)MROWS * DMODEL];
__device__ __half g_q [(size_t)MROWS * DMODEL];
__device__ __half g_kv[(size_t)MROWS * 2 * DMODEL];
__device__ __half g_o [(size_t)MROWS * DMODEL];
__device__ __half g_qw [DMODEL * DMODEL];
__device__ __half g_kvw[2 * DMODEL * DMODEL];
__device__ __half g_pw [DMODEL * DMODEL];
__device__ float  g_qb2[DMODEL];

// ---------------- helpers ----------------
__device__ __forceinline__ void mma16(float* c, const uint32_t* a, const uint32_t* b) {
    asm volatile(
        "mma.sync.aligned.m16n8k16.row.col.f32.f16.f16.f32 "
        "{%0,%1,%2,%3}, {%4,%5,%6,%7}, {%8,%9}, {%0,%1,%2,%3};\n"
        : "+f"(c[0]), "+f"(c[1]), "+f"(c[2]), "+f"(c[3])
        : "r"(a[0]), "r"(a[1]), "r"(a[2]), "r"(a[3]), "r"(b[0]), "r"(b[1]));
}

__device__ __forceinline__ void ldsm4(uint32_t saddr, uint32_t* r) {
    asm volatile("ldmatrix.sync.aligned.m8n8.x4.shared.b16 {%0,%1,%2,%3}, [%4];"
                 : "=r"(r[0]), "=r"(r[1]), "=r"(r[2]), "=r"(r[3]) : "r"(saddr));
}

__device__ __forceinline__ void ldsm4t(uint32_t saddr, uint32_t* r) {
    asm volatile("ldmatrix.sync.aligned.m8n8.x4.trans.shared.b16 {%0,%1,%2,%3}, [%4];"
                 : "=r"(r[0]), "=r"(r[1]), "=r"(r[2]), "=r"(r[3]) : "r"(saddr));
}

__device__ __forceinline__ void cp16(uint32_t saddr, const void* gptr) {
    asm volatile("cp.async.cg.shared.global [%0], [%1], 16;\n"
                 :: "r"(saddr), "l"(gptr) : "memory");
}

__device__ __forceinline__ void cp16z(uint32_t saddr, const void* gptr, int src_bytes) {
    asm volatile("cp.async.cg.shared.global [%0], [%1], 16, %2;\n"
                 :: "r"(saddr), "l"(gptr), "r"(src_bytes) : "memory");
}

__device__ __forceinline__ uint32_t pack2h(float a, float b) {
    __half2 h = __floats2half2_rn(a, b);
    return *(uint32_t*)&h;
}

__device__ __forceinline__ void ex2x2(uint32_t& x) {
    asm volatile("ex2.approx.f16x2 %0, %0;" : "+r"(x));
}

__device__ __forceinline__ float2 h22f2(uint32_t x) {
    return __half22float2(*(__half2*)&x);
}

__device__ __forceinline__ float4 ldcs4(const float4* p) {
    return __ldcs(p);
}

// ---------------- weight conversion (qw*S*log2e, kvw, pw, q_b) -----------------
#define C4 (DMODEL / 4)
#define C8 (DMODEL / 8)
#define WN4 (DMODEL * DMODEL / 4)
#define WCH (WN4 / 2)
#define QSCL (ATT_SCALE * LOG2E)
#define CW_TOTAL (4 * WCH + DMODEL / 4)

__device__ __forceinline__ uint4 cvt8(float4 a0, float4 a1, float4 p0, float4 p1) {
    uint4 o;
    o.x = pack2h(a0.x + p0.x, a0.y + p0.y);
    o.y = pack2h(a0.z + p0.z, a0.w + p0.w);
    o.z = pack2h(a1.x + p1.x, a1.y + p1.y);
    o.w = pack2h(a1.z + p1.z, a1.w + p1.w);
    return o;
}

__device__ __forceinline__ uint4 cvt8s(float4 a0, float4 a1, float s) {
    uint4 o;
    o.x = pack2h(a0.x * s, a0.y * s);
    o.y = pack2h(a0.z * s, a0.w * s);
    o.z = pack2h(a1.x * s, a1.y * s);
    o.w = pack2h(a1.z * s, a1.w * s);
    return o;
}

__global__ void conv_w_kernel(const float4* __restrict__ q_w,
                              const float4* __restrict__ kv_w,
                              const float4* __restrict__ proj_w,
                              const float4* __restrict__ q_b,
                              uint4* __restrict__ qw, uint4* __restrict__ kvw,
                              uint4* __restrict__ pw, float4* __restrict__ qb2) {
    int i = blockIdx.x * blockDim.x + threadIdx.x;
    if (i < WCH) {
        qw[i] = cvt8s(ldcs4(q_w + 2 * i), ldcs4(q_w + 2 * i + 1), QSCL);
    } else if (i < 3 * WCH) {
        int j = i - WCH;
        kvw[j] = cvt8s(ldcs4(kv_w + 2 * j), ldcs4(kv_w + 2 * j + 1), 1.f);
    } else if (i < 4 * WCH) {
        int j = i - 3 * WCH;
        pw[j] = cvt8s(ldcs4(proj_w + 2 * j), ldcs4(proj_w + 2 * j + 1), 1.f);
    } else if (i < CW_TOTAL) {
        int j = i - 4 * WCH;
        float4 v = q_b[j];
        v.x *= QSCL; v.y *= QSCL; v.z *= QSCL; v.w *= QSCL;
        qb2[j] = v;
    }
}

// ---------------- activation prep for one bt-quarter (rows [m0, m0+QROWS)) -----
#define QTCH (QROWS * C8)
#define PA_TOTAL (2 * QTCH)

__global__ void prep_act_kernel(const float4* __restrict__ t_x,
                                const float4* __restrict__ s_x,
                                const float4* __restrict__ vmae_pos,
                                const float4* __restrict__ clip_pos,
                                uint4* __restrict__ At, uint4* __restrict__ As,
                                int m0) {
    int idx = blockIdx.x * blockDim.x + threadIdx.x;
    if (idx < QTCH) {
        int m = m0 + idx / C8;
        int c = idx - (idx / C8) * C8;
        const float4* a = t_x + (size_t)m * C4 + 2 * c;
        const float4* p = vmae_pos + (m % NTOK) * C4 + 2 * c;
        float4 a0 = ldcs4(a), a1 = ldcs4(a + 1);
        float4 p0 = p[0], p1 = p[1];
        At[(size_t)m * C8 + c] = cvt8(a0, a1, p0, p1);
    } else if (idx < 2 * QTCH) {
        int i = idx - QTCH;
        int m = m0 + i / C8;
        int c = i - (i / C8) * C8;
        int src_row = m + m / NTOK + 1;       // skip CLS each frame
        const float4* a = s_x + (size_t)src_row * C4 + 2 * c;
        const float4* p = clip_pos + (m % NTOK) * C4 + 2 * c;
        float4 a0 = ldcs4(a), a1 = ldcs4(a + 1);
        float4 p0 = p[0], p1 = p[1];
        As[(size_t)m * C8 + c] = cvt8(a0, a1, p0, p1);
    }
}

// ---------------- fp16 GEMM core (frozen): 256 thr, 8 warps 32x64, BK=64 --------
#define LDHB 128
#define GTILE_B (128 * LDHB)        // 16384 B
#define GSTG_B  (2 * GTILE_B)       // 32768 B
#define GSMEM   (3 * GSTG_B)        // 98304 B

__device__ __forceinline__ void fill_chunk_f16(uint32_t sbase, int stage,
                                               const __half* A, const __half* W,
                                               int bm, int bn, int kt, int tid, int qc) {
    uint32_t ab = sbase + stage * GSTG_B;
    uint32_t bb = ab + GTILE_B;
    #pragma unroll
    for (int it = 2 * qc; it < 2 * qc + 2; it++) {
        int c = tid + it * 256;
        int row, ch;
        if (c < 1024) {
            row = c >> 3; ch = c & 7;
            const __half* g = A + (size_t)(bm * 128 + row) * DMODEL + kt * 64 + ch * 8;
            cp16(ab + (row << 7) + (((uint32_t)(ch ^ (row & 7))) << 4), g);
        } else {
            int c2 = c - 1024;
            row = c2 >> 3; ch = c2 & 7;
            const __half* g = W + (size_t)(bn * 128 + row) * DMODEL + kt * 64 + ch * 8;
            cp16(bb + (row << 7) + (((uint32_t)(ch ^ (row & 7))) << 4), g);
        }
    }
}

template <bool HALF_OUT>
__device__ __forceinline__ void gemm_core(const __half* __restrict__ A,
                                          const __half* __restrict__ W,
                                          const float* __restrict__ bias,
                                          void* __restrict__ Cout,
                                          int Ncols, int bn, int bm,
                                          uint32_t sbase) {
    const int tid  = threadIdx.x;
    const int lane = tid & 31;
    const int w    = tid >> 5;
    const int wm   = (w & 3) * 32;
    const int wn   = (w >> 2) * 64;
    const int gr   = lane >> 2;
    const int tg   = lane & 3;
    const int lr   = lane & 15;
    const int lh   = lane >> 4;
    const uint32_t sw = (uint32_t)(lr & 7);

    uint32_t arow[2], brow[4];
    #pragma unroll
    for (int i = 0; i < 2; i++)  arow[i] = (uint32_t)(wm + i * 16 + lr) << 7;
    #pragma unroll
    for (int jb = 0; jb < 4; jb++) brow[jb] = (uint32_t)(wn + jb * 16 + lr) << 7;

    float acc[2][8][4];
    #pragma unroll
    for (int i = 0; i < 2; i++)
        #pragma unroll
        for (int j = 0; j < 8; j++)
            #pragma unroll
            for (int r = 0; r < 4; r++) acc[i][j][r] = 0.f;

    #pragma unroll
    for (int pk = 0; pk < 2; pk++) {
        #pragma unroll
        for (int qc = 0; qc < 4; qc++)
            fill_chunk_f16(sbase, pk, A, W, bm, bn, pk, tid, qc);
        asm volatile("cp.async.commit_group;\n" ::: "memory");
    }

    for (int kt = 0; kt < 12; kt++) {
        if (kt < 11) asm volatile("cp.async.wait_group 1;\n" ::: "memory");
        else         asm volatile("cp.async.wait_group 0;\n" ::: "memory");
        __syncthreads();

        const bool do_fill = (kt + 2 < 12);
        const int fstage = (kt + 2) % 3;

        const uint32_t sAs = sbase + (uint32_t)((kt % 3) * GSTG_B);
        const uint32_t sBs = sAs + GTILE_B;

        #pragma unroll
        for (int k16 = 0; k16 < 4; k16++) {
            if (do_fill)
                fill_chunk_f16(sbase, fstage, A, W, bm, bn, kt + 2, tid, k16);

            const uint32_t pc = (((uint32_t)(2 * k16 + lh)) ^ sw) << 4;
            uint32_t a[2][4], bb[4][4];
            #pragma unroll
            for (int i = 0; i < 2; i++)
                ldsm4(sAs + arow[i] + pc, a[i]);
            #pragma unroll
            for (int jb = 0; jb < 4; jb++)
                ldsm4(sBs + brow[jb] + pc, bb[jb]);
            #pragma unroll
            for (int i = 0; i < 2; i++)
                #pragma unroll
                for (int j = 0; j < 8; j++) {
                    uint32_t bfrag[2];
                    bfrag[0] = bb[j >> 1][(j & 1)];
                    bfrag[1] = bb[j >> 1][(j & 1) + 2];
                    mma16(acc[i][j], a[i], bfrag);
                }
        }
        if (do_fill)
            asm volatile("cp.async.commit_group;\n" ::: "memory");
    }

    #pragma unroll
    for (int i = 0; i < 2; i++) {
        #pragma unroll
        for (int j = 0; j < 8; j++) {
            int row0 = bm * 128 + wm + i * 16 + gr;
            int col  = bn * 128 + wn + j * 8 + tg * 2;
            float b0 = bias[col], b1 = bias[col + 1];
            if (HALF_OUT) {
                __half* Ch = (__half*)Cout;
                *(__half2*)(Ch + (size_t)row0 * Ncols + col) =
                    __floats2half2_rn(acc[i][j][0] + b0, acc[i][j][1] + b1);
                *(__half2*)(Ch + (size_t)(row0 + 8) * Ncols + col) =
                    __floats2half2_rn(acc[i][j][2] + b0, acc[i][j][3] + b1);
            } else {
                float* Cf = (float*)Cout;
                float* p0 = Cf + (size_t)row0 * Ncols + col;
                float* p1 = Cf + (size_t)(row0 + 8) * Ncols + col;
                p0[0] = acc[i][j][0] + b0;
                p0[1] = acc[i][j][1] + b1;
                p1[0] = acc[i][j][2] + b0;
                p1[1] = acc[i][j][3] + b1;
            }
        }
    }
}

// fused q+kv projection for one bt-quarter: bn<6 -> q GEMM, else kv GEMM
__global__ __launch_bounds__(256, 2)
void gemm_qkv_kernel(const __half* __restrict__ At, const __half* __restrict__ qw,
                     const float* __restrict__ qb2, __half* __restrict__ qh,
                     const __half* __restrict__ As, const __half* __restrict__ kvw,
                     const float* __restrict__ kv_b, __half* __restrict__ kvh,
                     int bm_base) {
    extern __shared__ __half sh[];
    const uint32_t sbase = (uint32_t)__cvta_generic_to_shared(sh);
    int bm = bm_base + blockIdx.y;
    if (blockIdx.x < 6)
        gemm_core<true>(At, qw, qb2, qh, DMODEL, blockIdx.x, bm, sbase);
    else
        gemm_core<true>(As, kvw, kv_b, kvh, 2 * DMODEL, blockIdx.x - 6, bm, sbase);
}

__global__ __launch_bounds__(256, 2)
void gemm_proj_kernel(const __half* __restrict__ A, const __half* __restrict__ W,
                      const float* __restrict__ bias, float* __restrict__ C,
                      int bm_base) {
    extern __shared__ __half sh[];
    const uint32_t sbase = (uint32_t)__cvta_generic_to_shared(sh);
    gemm_core<false>(A, W, bias, C, DMODEL, blockIdx.x, bm_base + blockIdx.y, sbase);
}

// ---------------- fp16 flash attention: 2 CTAs per (bt,h), 7 warps x 16 q-rows ----
#define ATW 224
#define AQH 112
#define AKV 224
#define SK_OFF (AQH * 128)               // 14336
#define SV_OFF (SK_OFF + AKV * 128)      // 43008
#define ASMEM (SV_OFF + AKV * 128)       // 71680 B

__global__ __launch_bounds__(ATW, 3)
void attn_mma_kernel(const __half* __restrict__ q, const __half* __restrict__ kv,
                     __half* __restrict__ o, int bt_base) {
    extern __shared__ __half smh[];
    const uint32_t sbase = (uint32_t)__cvta_generic_to_shared(smh);
    const uint32_t sQa = sbase;
    const uint32_t sKa = sbase + SK_OFF;
    const uint32_t sVa = sbase + SV_OFF;

    const int b2   = blockIdx.x;
    const int bt   = bt_base + b2 / (2 * NHEAD);
    const int r2   = b2 % (2 * NHEAD);
    const int h    = r2 >> 1;
    const int half = r2 & 1;
    const int tid  = threadIdx.x;
    const int lane = tid & 31;
    const int w    = tid >> 5;        // 0..6
    const int gr   = lane >> 2;
    const int tg   = lane & 3;
    const int lr   = lane & 15;
    const int lh   = lane >> 4;
    const uint32_t sw = (uint32_t)(lr & 7);

    // ---- stage Q (112 rows) + K (224 rows): commit group 0 ----
    for (int idx = tid; idx < AQH * 8; idx += ATW) {
        int r = idx >> 3, ch = idx & 7;
        int grow = half * AQH + r;
        int sz = (grow < NTOK) ? 16 : 0;
        int rr = (grow < NTOK) ? grow : 0;
        uint32_t soff = ((uint32_t)r << 7) + (((uint32_t)(ch ^ (r & 7))) << 4);
        cp16z(sQa + soff, q + ((size_t)bt * NTOK + rr) * DMODEL + h * HDIM + ch * 8, sz);
    }
    for (int idx = tid; idx < AKV * 8; idx += ATW) {
        int r = idx >> 3, ch = idx & 7;
        int sz = (r < NTOK) ? 16 : 0;
        int rr = (r < NTOK) ? r : 0;
        uint32_t soff = ((uint32_t)r << 7) + (((uint32_t)(ch ^ (r & 7))) << 4);
        cp16z(sKa + soff, kv + ((size_t)bt * NTOK + rr) * (2 * DMODEL) + h * HDIM + ch * 8, sz);
    }
    asm volatile("cp.async.commit_group;\n" ::: "memory");

    // ---- stage V (224 rows): commit group 1 ----
    for (int idx = tid; idx < AKV * 8; idx += ATW) {
        int r = idx >> 3, ch = idx & 7;
        int sz = (r < NTOK) ? 16 : 0;
        int rr = (r < NTOK) ? r : 0;
        uint32_t soff = ((uint32_t)r << 7) + (((uint32_t)(ch ^ (r & 7))) << 4);
        cp16z(sVa + soff, kv + ((size_t)bt * NTOK + rr) * (2 * DMODEL) + DMODEL + h * HDIM + ch * 8, sz);
    }
    asm volatile("cp.async.commit_group;\n" ::: "memory");

    asm volatile("cp.async.wait_group 1;\n" ::: "memory");
    __syncthreads();

    // ---- preload Q A-fragments (16 rows per warp, 4 k16 chunks) ----
    const int qb = w * 16;
    const uint32_t qrow = (uint32_t)(qb + lr) << 7;
    uint32_t qa[4][4];
    #pragma unroll
    for (int kk = 0; kk < 4; kk++)
        ldsm4(sQa + qrow + ((((uint32_t)(2 * kk + lh)) ^ sw) << 4), qa[kk]);

    float oacc[8][4];
    #pragma unroll
    for (int n = 0; n < 8; n++)
        #pragma unroll
        for (int r = 0; r < 4; r++) oacc[n][r] = 0.f;
    float lsum[2] = {0.f, 0.f};

    bool v_waited = false;

    for (int kt = 0; kt < 7; kt++) {
        float s[4][4];
        #pragma unroll
        for (int j = 0; j < 4; j++)
            #pragma unroll
            for (int r = 0; r < 4; r++) s[j][r] = 0.f;

        #pragma unroll
        for (int kk = 0; kk < 4; kk++) {
            const uint32_t pc = (((uint32_t)(2 * kk + lh)) ^ sw) << 4;
            uint32_t kb[2][4];
            #pragma unroll
            for (int jb = 0; jb < 2; jb++)
                ldsm4(sKa + (((uint32_t)(kt * 32 + jb * 16 + lr)) << 7) + pc, kb[jb]);
            #pragma unroll
            for (int j = 0; j < 4; j++) {
                uint32_t bfrag[2];
                bfrag[0] = kb[j >> 1][(j & 1)];
                bfrag[1] = kb[j >> 1][(j & 1) + 2];
                mma16(s[j], qa[kk], bfrag);
            }
        }

        if (kt == 6) {
            #pragma unroll
            for (int j = 0; j < 4; j++) {
                int c0 = 192 + j * 8 + 2 * tg;
                if (c0 >= NTOK)     { s[j][0] = s[j][2] = -1e30f; }
                if (c0 + 1 >= NTOK) { s[j][1] = s[j][3] = -1e30f; }
            }
        }

        if (!v_waited) {
            asm volatile("cp.async.wait_group 0;\n" ::: "memory");
            __syncthreads();
            v_waited = true;
        }

        #pragma unroll
        for (int ck = 0; ck < 2; ck++) {
            uint32_t pa[4];
            int j0 = ck * 2;
            pa[0] = pack2h(s[j0][0],     s[j0][1]);
            pa[1] = pack2h(s[j0][2],     s[j0][3]);
            pa[2] = pack2h(s[j0 + 1][0], s[j0 + 1][1]);
            pa[3] = pack2h(s[j0 + 1][2], s[j0 + 1][3]);
            ex2x2(pa[0]); ex2x2(pa[1]); ex2x2(pa[2]); ex2x2(pa[3]);

            float2 f0 = h22f2(pa[0]), f2 = h22f2(pa[2]);
            lsum[0] += (f0.x + f0.y) + (f2.x + f2.y);
            float2 f1 = h22f2(pa[1]), f3 = h22f2(pa[3]);
            lsum[1] += (f1.x + f1.y) + (f3.x + f3.y);

            int kr = kt * 32 + ck * 16;
            uint32_t vbb[4][4];
            #pragma unroll
            for (int nb = 0; nb < 4; nb++)
                ldsm4t(sVa + (((uint32_t)(kr + lr)) << 7) +
                       ((((uint32_t)(2 * nb + lh)) ^ sw) << 4), vbb[nb]);

            #pragma unroll
            for (int n = 0; n < 8; n++) {
                uint32_t vb[2];
                vb[0] = vbb[n >> 1][(n & 1) * 2];
                vb[1] = vbb[n >> 1][(n & 1) * 2 + 1];
                mma16(oacc[n], pa, vb);
            }
        }
    }

    #pragma unroll
    for (int hl = 0; hl < 2; hl++) {
        lsum[hl] += __shfl_xor_sync(0xffffffffu, lsum[hl], 1);
        lsum[hl] += __shfl_xor_sync(0xffffffffu, lsum[hl], 2);
    }

    #pragma unroll
    for (int hl = 0; hl < 2; hl++) {
        float inv = 1.f / lsum[hl];
        int row = half * AQH + qb + gr + 8 * hl;
        if (row < NTOK) {
            __half* dst = o + ((size_t)bt * NTOK + row) * DMODEL + h * HDIM;
            #pragma unroll
            for (int n = 0; n < 8; n++) {
                *(__half2*)(dst + n * 8 + 2 * tg) =
                    __floats2half2_rn(oacc[n][2 * hl] * inv, oacc[n][2 * hl + 1] * inv);
            }
        }
    }
}

// ---------------- launch: four bt-quarter chains pipelined across streams ------
extern "C" void kernel_launch(void* const* d_in, const int* in_sizes, int n_in,
                              void* d_out, int out_size) {
    const float* s_x      = (const float*)d_in[0];
    const float* t_x      = (const float*)d_in[1];
    const float* clip_pos = (const float*)d_in[2];
    const float* vmae_pos = (const float*)d_in[3];
    const float* q_w      = (const float*)d_in[4];
    const float* q_b      = (const float*)d_in[5];
    const float* kv_w     = (const float*)d_in[6];
    const float* kv_b     = (const float*)d_in[7];
    const float* proj_w   = (const float*)d_in[8];
    const float* proj_b   = (const float*)d_in[9];
    float* out = (float*)d_out;
    (void)in_sizes; (void)n_in; (void)out_size;

    __half *At, *As_, *qh, *kvh, *ob, *qw, *kvw, *pw;
    float *qb2;
    cudaGetSymbolAddress((void**)&At,  g_At);
    cudaGetSymbolAddress((void**)&As_, g_As);
    cudaGetSymbolAddress((void**)&qh,  g_q);
    cudaGetSymbolAddress((void**)&kvh, g_kv);
    cudaGetSymbolAddress((void**)&ob,  g_o);
    cudaGetSymbolAddress((void**)&qw,  g_qw);
    cudaGetSymbolAddress((void**)&kvw, g_kvw);
    cudaGetSymbolAddress((void**)&pw,  g_pw);
    cudaGetSymbolAddress((void**)&qb2, g_qb2);

    cudaFuncSetAttribute(gemm_qkv_kernel,  cudaFuncAttributeMaxDynamicSharedMemorySize, GSMEM);
    cudaFuncSetAttribute(gemm_proj_kernel, cudaFuncAttributeMaxDynamicSharedMemorySize, GSMEM);
    cudaFuncSetAttribute(attn_mma_kernel,  cudaFuncAttributeMaxDynamicSharedMemorySize, ASMEM);

    // fork resources (created each call; destroyed only outside capture)
    cudaStream_t st[3];
    cudaEvent_t eF, eW, eJ[3];
    for (int i = 0; i < 3; i++) cudaStreamCreateWithFlags(&st[i], cudaStreamNonBlocking);
    cudaEventCreateWithFlags(&eF, cudaEventDisableTiming);
    cudaEventCreateWithFlags(&eW, cudaEventDisableTiming);
    for (int i = 0; i < 3; i++) cudaEventCreateWithFlags(&eJ[i], cudaEventDisableTiming);

    const int paBlocks = (PA_TOTAL + 255) / 256;
    const int bmQ = QROWS / 128;   // 49 row-blocks per quarter

    // ---- fork point: side streams join capture graph at the root ----
    cudaEventRecord(eF, 0);
    for (int i = 0; i < 3; i++) cudaStreamWaitEvent(st[i], eF, 0);

    // ---- main stream: weights, then chunk 0 chain ----
    conv_w_kernel<<<(CW_TOTAL + 255) / 256, 256>>>(
        (const float4*)q_w, (const float4*)kv_w, (const float4*)proj_w,
        (const float4*)q_b, (uint4*)qw, (uint4*)kvw, (uint4*)pw, (float4*)qb2);
    cudaEventRecord(eW, 0);

    prep_act_kernel<<<paBlocks, 256>>>(
        (const float4*)t_x, (const float4*)s_x,
        (const float4*)vmae_pos, (const float4*)clip_pos,
        (uint4*)At, (uint4*)As_, 0);
    gemm_qkv_kernel<<<dim3(18, bmQ), 256, GSMEM>>>(
        At, qw, qb2, qh, As_, kvw, kv_b, kvh, 0);
    attn_mma_kernel<<<QBT * NHEAD * 2, ATW, ASMEM>>>(qh, kvh, ob, 0);
    gemm_proj_kernel<<<dim3(DMODEL / 128, bmQ), 256, GSMEM>>>(ob, pw, proj_b, out, 0);

    // ---- side streams: chunks 1..3 (prep independent; qkv gated on weights) ----
    for (int i = 0; i < 3; i++) {
        int ck = i + 1;
        int m0 = ck * QROWS;
        prep_act_kernel<<<paBlocks, 256, 0, st[i]>>>(
            (const float4*)t_x, (const float4*)s_x,
            (const float4*)vmae_pos, (const float4*)clip_pos,
            (uint4*)At, (uint4*)As_, m0);
        cudaStreamWaitEvent(st[i], eW, 0);
        gemm_qkv_kernel<<<dim3(18, bmQ), 256, GSMEM, st[i]>>>(
            At, qw, qb2, qh, As_, kvw, kv_b, kvh, ck * bmQ);
        attn_mma_kernel<<<QBT * NHEAD * 2, ATW, ASMEM, st[i]>>>(qh, kvh, ob, ck * QBT);
        gemm_proj_kernel<<<dim3(DMODEL / 128, bmQ), 256, GSMEM, st[i]>>>(
            ob, pw, proj_b, out, ck * bmQ);
        cudaEventRecord(eJ[i], st[i]);
    }

    // ---- join ----
    for (int i = 0; i < 3; i++) cudaStreamWaitEvent(0, eJ[i], 0);

    // destroy fork resources only outside capture
    cudaStreamCaptureStatus cs = cudaStreamCaptureStatusNone;
    cudaError_t qerr = cudaStreamIsCapturing(0, &cs);
    if (qerr == cudaSuccess && cs == cudaStreamCaptureStatusNone) {
        for (int i = 0; i < 3; i++) cudaStreamDestroy(st[i]);
        cudaEventDestroy(eF);
        cudaEventDestroy(eW);
        for (int i = 0; i < 3; i++) cudaEventDestroy(eJ[i]);
    }
}